// round 12
// baseline (speedup 1.0000x reference)
#include <cuda_runtime.h>
#include <math.h>
#include <stdint.h>

#define Lq 1024
#define Rr 8192
#define NBS 128
#define NTS 256

typedef unsigned long long u64;

// ---------------- scratch (device globals; no allocs allowed) ----------------
__device__ float g_atn[(size_t)Lq * Rr];     // [l][r] 32MB, L2-resident
__device__ float g_accP[7][12*32];           // per-step grad sums, 128B element stride
__device__ unsigned g_arr[7];                // per-step arrival counters
__device__ unsigned g_cnt;                   // init gridbar counter
__device__ unsigned g_sense;                 // init gridbar sense

__device__ __forceinline__ float frcp(float x) {
    float y; asm("rcp.approx.f32 %0, %1;" : "=f"(y) : "f"(x)); return y;
}
__device__ __forceinline__ u64 pk2(float lo, float hi) {
    u64 r; asm("mov.b64 %0, {%1, %2};" : "=l"(r) : "f"(lo), "f"(hi)); return r;
}
__device__ __forceinline__ void up2(u64 v, float& a, float& b) {
    asm("mov.b64 {%0, %1}, %2;" : "=f"(a), "=f"(b) : "l"(v));
}
__device__ __forceinline__ u64 add2(u64 a, u64 b) {
    u64 d; asm("add.rn.f32x2 %0, %1, %2;" : "=l"(d) : "l"(a), "l"(b)); return d;
}
__device__ __forceinline__ u64 mul2(u64 a, u64 b) {
    u64 d; asm("mul.rn.f32x2 %0, %1, %2;" : "=l"(d) : "l"(a), "l"(b)); return d;
}
__device__ __forceinline__ u64 fma2(u64 a, u64 b, u64 c) {
    u64 d; asm("fma.rn.f32x2 %0, %1, %2, %3;" : "=l"(d) : "l"(a), "l"(b), "l"(c)); return d;
}
__device__ __forceinline__ unsigned ldacq(const unsigned* p) {
    unsigned v; asm volatile("ld.acquire.gpu.u32 %0, [%1];" : "=r"(v) : "l"(p) : "memory"); return v;
}
__device__ __forceinline__ float ldacqf(const float* p) {
    float v; asm volatile("ld.acquire.gpu.f32 %0, [%1];" : "=f"(v) : "l"(p) : "memory"); return v;
}
__device__ __forceinline__ void strel(unsigned* p, unsigned v) {
    asm volatile("st.release.gpu.u32 [%0], %1;" :: "l"(p), "r"(v) : "memory");
}
__device__ __forceinline__ void cpasync16(unsigned dst, const void* src) {
    asm volatile("cp.async.cg.shared.global [%0], [%1], 16;" :: "r"(dst), "l"(src) : "memory");
}

// sense-reversing grid barrier (once at init); self-resetting across replays.
__device__ __forceinline__ void gridbar(unsigned& sense) {
    __syncthreads();
    if (threadIdx.x == 0) {
        unsigned ns = sense ^ 1u;
        __threadfence();
        unsigned old = atomicAdd(&g_cnt, 1u);
        if (old == NBS - 1u) {
            atomicExch(&g_cnt, 0u);
            strel(&g_sense, ns);
        } else {
            while (ldacq(&g_sense) != ns) {}
        }
    }
    __syncthreads();
    sense ^= 1u;
}

// LAPACK-convention Householder QR of a 3x3 (geqrf+orgqr signs).
__device__ void qr3(const float* A, float* Q, float* Rm) {
    float M[9];
    #pragma unroll
    for (int i = 0; i < 9; i++) M[i] = A[i];
    float Qa[9] = {1.f,0.f,0.f, 0.f,1.f,0.f, 0.f,0.f,1.f};
    #pragma unroll
    for (int k = 0; k < 2; k++) {
        float alpha = M[k*3+k];
        float xn2 = 0.f;
        for (int j = k+1; j < 3; j++) xn2 += M[j*3+k]*M[j*3+k];
        if (xn2 == 0.f) continue;
        float nrm  = sqrtf(alpha*alpha + xn2);
        float beta = (alpha >= 0.f) ? -nrm : nrm;
        float v[3] = {0.f,0.f,0.f};
        v[k] = 1.f;
        float denom = alpha - beta;
        for (int j = k+1; j < 3; j++) v[j] = M[j*3+k] / denom;
        float tau = (beta - alpha) / beta;
        for (int c = k; c < 3; c++) {
            float s = 0.f;
            for (int j = k; j < 3; j++) s += v[j]*M[j*3+c];
            s *= tau;
            for (int j = k; j < 3; j++) M[j*3+c] -= s*v[j];
        }
        M[k*3+k] = beta;
        for (int j = k+1; j < 3; j++) M[j*3+k] = 0.f;
        for (int i = 0; i < 3; i++) {
            float s = 0.f;
            for (int j = k; j < 3; j++) s += Qa[i*3+j]*v[j];
            s *= tau;
            for (int j = k; j < 3; j++) Qa[i*3+j] -= s*v[j];
        }
    }
    #pragma unroll
    for (int i = 0; i < 9; i++) { Q[i] = Qa[i]; Rm[i] = M[i]; }
}

__device__ __forceinline__ float blockSum(float v, float* s8) {
    #pragma unroll
    for (int o = 16; o > 0; o >>= 1) v += __shfl_down_sync(0xffffffffu, v, o);
    __syncthreads();
    if ((threadIdx.x & 31) == 0) s8[threadIdx.x >> 5] = v;
    __syncthreads();
    float t = s8[0];
    #pragma unroll
    for (int i = 1; i < 8; i++) t += s8[i];
    return t;
}

// ---------------- atn[l][r] = dot(lig_feat[l], rec_feat[r]) -------------------
// (R11 proven) 64l x 64r tile, XOR-swizzled float4 smem, packed f32x2 product.
__global__ void __launch_bounds__(256) k_atn(const float* __restrict__ lig_feat,
                                             const float* __restrict__ rec_feat) {
    __shared__ float4 ligs4[64*16];
    __shared__ float4 recs4[64*16];
    int tid = threadIdx.x;
    int tx = tid & 15;       // r-lane
    int ty = tid >> 4;       // l-group
    int r0 = blockIdx.x * 64;
    int l0 = blockIdx.y * 64;
    const float4* ligf4 = (const float4*)lig_feat;
    const float4* recf4 = (const float4*)rec_feat;
    #pragma unroll
    for (int i = 0; i < 4; i++) {
        int idx = i*256 + tid;
        int row = idx >> 4;
        int f4  = idx & 15;
        ligs4[row*16 + (f4 ^ (row & 7))] = ligf4[(size_t)(l0+row)*16 + f4];
        recs4[row*16 + (f4 ^ (row & 7))] = recf4[(size_t)(r0+row)*16 + f4];
    }
    __syncthreads();
    u64 acc[4][4];
    #pragma unroll
    for (int i = 0; i < 4; i++)
        #pragma unroll
        for (int j = 0; j < 4; j++) acc[i][j] = 0ull;

    #pragma unroll
    for (int f4 = 0; f4 < 16; f4++) {
        ulonglong2 a[4], b[4];
        #pragma unroll
        for (int i = 0; i < 4; i++) {
            int row = tx + 16*i;
            a[i] = *(const ulonglong2*)&recs4[row*16 + (f4 ^ (row & 7))];
        }
        #pragma unroll
        for (int j = 0; j < 4; j++) {
            int row = ty*4 + j;
            b[j] = *(const ulonglong2*)&ligs4[row*16 + (f4 ^ (row & 7))];
        }
        #pragma unroll
        for (int i = 0; i < 4; i++)
            #pragma unroll
            for (int j = 0; j < 4; j++) {
                acc[i][j] = fma2(a[i].x, b[j].x, acc[i][j]);
                acc[i][j] = fma2(a[i].y, b[j].y, acc[i][j]);
            }
    }
    #pragma unroll
    for (int j = 0; j < 4; j++) {
        size_t rowbase = (size_t)(l0 + ty*4 + j) * Rr + r0;
        #pragma unroll
        for (int i = 0; i < 4; i++) {
            float lo, hi; up2(acc[i][j], lo, hi);
            g_atn[rowbase + tx + 16*i] = lo + hi;
        }
    }
}

// process one u64 (2 r's) for both l's, accumulator set p
#define PAIR_BODY(Av0, Av1, cx, cy, cz, p)                                      \
    {                                                                           \
        u64 dx = add2(X0, cx), dy = add2(Y0, cy), dz = add2(Z0, cz);            \
        u64 d = mul2(dx, dx); d = fma2(dy, dy, d); d = fma2(dz, dz, d);         \
        float dl, dh; up2(d, dl, dh);                                           \
        u64 inv = pk2(frcp(dl), frcp(dh));                                      \
        u64 i4 = mul2(inv, inv);                                                \
        u64 wv = mul2(Av0, i4);                                                 \
        SW0[p] = add2(SW0[p], wv);                                              \
        AX0[p] = fma2(wv, cx, AX0[p]); AY0[p] = fma2(wv, cy, AY0[p]); AZ0[p] = fma2(wv, cz, AZ0[p]); \
        dx = add2(X1, cx); dy = add2(Y1, cy); dz = add2(Z1, cz);                \
        d = mul2(dx, dx); d = fma2(dy, dy, d); d = fma2(dz, dz, d);             \
        up2(d, dl, dh);                                                         \
        inv = pk2(frcp(dl), frcp(dh));                                          \
        i4 = mul2(inv, inv);                                                    \
        wv = mul2(Av1, i4);                                                     \
        SW1[p] = add2(SW1[p], wv);                                              \
        AX1[p] = fma2(wv, cx, AX1[p]); AY1[p] = fma2(wv, cy, AY1[p]); AZ1[p] = fma2(wv, cz, AZ1[p]); \
    }

// prefetch chunk c (128 r's) into ring stage (c&3): 2 x 16B per lane
#define PREFETCH(c)                                                             \
    {                                                                           \
        unsigned d0 = sb_w + (((c) & 3)*256 + lane*4)*4;                        \
        cpasync16(d0,       ga0 + (c)*128 + lane*4);                            \
        cpasync16(d0 + 512, ga1 + (c)*128 + lane*4);                            \
        asm volatile("cp.async.commit_group;" ::: "memory");                    \
    }

// compute chunk c from ring stage (c&3): 4 r per lane x 2 l, acc set (c&1)
#define CHUNK(c)                                                                \
    {                                                                           \
        const float4 a0 = *(const float4*)(s_atn_w + ((c) & 3)*256 + lane*4);   \
        const float4 a1 = *(const float4*)(s_atn_w + ((c) & 3)*256 + 128 + lane*4); \
        int idx = (c)*32 + lane;                                                \
        ulonglong2 vx = pX[idx], vy = pY[idx], vz = pZ[idx];                    \
        PAIR_BODY(pk2(a0.x,a0.y), pk2(a1.x,a1.y), vx.x, vy.x, vz.x, (c)&1);     \
        PAIR_BODY(pk2(a0.z,a0.w), pk2(a1.z,a1.w), vx.y, vy.y, vz.y, (c)&1);     \
    }

// ---------------- persistent kernel: preps + all 8 steps ----------------------
__global__ void __launch_bounds__(NTS, 1) k_steps(const float* __restrict__ lig_coord,
                                                  const float* __restrict__ rec_coord,
                                                  const float* __restrict__ pre_rot,
                                                  const float* __restrict__ trans,
                                                  float* __restrict__ out) {
    extern __shared__ float sm[];
    u64* cX = (u64*)sm;                  // [4096] packed r-pairs of (mean - x)
    u64* cY = cX + 4096;
    u64* cZ = cY + 4096;
    float* s_atn = sm + 24576;           // [8 warps][4 stages][2 l][128 r] = 32KB
    __shared__ float s_red[8];
    __shared__ float s_ws[8][8];
    __shared__ float s_red12[8][12];
    __shared__ float s_ligc[8][3];
    __shared__ float s_upd[12];          // current-step Q(9)+tr(3)
    __shared__ float s_t[12];            // fetched global gradient sums

    int tid = threadIdx.x, b = blockIdx.x;
    int w = tid >> 5, lane = tid & 31;
    int lp = w & 3, h = w >> 2;                // l-pair idx (0..3), r-half (0..1)
    int l0 = b*8 + lp*2;                       // warp handles l0, l0+1

    unsigned sense;
    { volatile unsigned* gs = &g_sense; sense = *gs; }

    // ---- rec means ----
    float sx = 0.f, sy = 0.f, sz = 0.f;
    for (int i = tid; i < Rr; i += NTS) {
        sx += rec_coord[3*i]; sy += rec_coord[3*i+1]; sz += rec_coord[3*i+2];
    }
    float mx = blockSum(sx, s_red) * (1.f/Rr);
    float my = blockSum(sy, s_red) * (1.f/Rr);
    float mz = blockSum(sz, s_red) * (1.f/Rr);

    // ---- build negated-centered coord arrays (4 r's per thread-iter) ----
    {
        const float4* rc4 = (const float4*)rec_coord;
        ulonglong2* vX = (ulonglong2*)cX;
        ulonglong2* vY = (ulonglong2*)cY;
        ulonglong2* vZ = (ulonglong2*)cZ;
        for (int p4 = tid; p4 < Rr/4; p4 += NTS) {
            float4 f0 = rc4[3*p4], f1 = rc4[3*p4+1], f2 = rc4[3*p4+2];
            ulonglong2 ox, oy, oz;
            ox.x = pk2(mx - f0.x, mx - f0.w);
            ox.y = pk2(mx - f1.z, mx - f2.y);
            oy.x = pk2(my - f0.y, my - f1.x);
            oy.y = pk2(my - f1.w, my - f2.z);
            oz.x = pk2(mz - f0.z, mz - f1.y);
            oz.y = pk2(mz - f2.x, mz - f2.w);
            vX[p4] = ox; vY[p4] = oy; vZ[p4] = oz;
        }
    }

    // ---- lig means + centered coords for this block's 8 l's ----
    float lsx = 0.f, lsy = 0.f, lsz = 0.f;
    for (int i = tid; i < Lq; i += NTS) {
        lsx += lig_coord[3*i]; lsy += lig_coord[3*i+1]; lsz += lig_coord[3*i+2];
    }
    float mlx = blockSum(lsx, s_red) * (1.f/Lq);
    float mly = blockSum(lsy, s_red) * (1.f/Lq);
    float mlz = blockSum(lsz, s_red) * (1.f/Lq);
    if (tid < 8) {
        int l = b*8 + tid;
        s_ligc[tid][0] = lig_coord[3*l]   - mlx;
        s_ligc[tid][1] = lig_coord[3*l+1] - mly;
        s_ligc[tid][2] = lig_coord[3*l+2] - mlz;
    }

    // ---- per-block optimizer state (identical in every block: deterministic) ----
    float pr[9], trv[3], Q[9], Rm[9];
    if (tid == 0) {
        #pragma unroll
        for (int i = 0; i < 9; i++) pr[i] = pre_rot[i];
        #pragma unroll
        for (int i = 0; i < 3; i++) trv[i] = trans[i] * 4.0f;   // TRANS_DIST
        qr3(pr, Q, Rm);
        #pragma unroll
        for (int i = 0; i < 9; i++) s_upd[i] = Q[i];
        #pragma unroll
        for (int i = 0; i < 3; i++) s_upd[9+i] = trv[i];
    }

    // ---- block 0 zeroes the per-step accumulators/counters ----
    if (b == 0) {
        for (int i = tid; i < 7*12*32; i += NTS) ((float*)g_accP)[i] = 0.f;
        if (tid < 7) g_arr[tid] = 0u;
    }
    gridbar(sense);   // accumulators zeroed + smem coords/params ready

    float lx0 = s_ligc[lp*2][0],   ly0 = s_ligc[lp*2][1],   lz0 = s_ligc[lp*2][2];
    float lx1 = s_ligc[lp*2+1][0], ly1 = s_ligc[lp*2+1][1], lz1 = s_ligc[lp*2+1][2];

    const float* ga0 = g_atn + (size_t)l0*Rr     + h*4096;
    const float* ga1 = g_atn + (size_t)(l0+1)*Rr + h*4096;
    const ulonglong2* pX = (const ulonglong2*)cX + h*1024;
    const ulonglong2* pY = (const ulonglong2*)cY + h*1024;
    const ulonglong2* pZ = (const ulonglong2*)cZ + h*1024;
    const float* s_atn_w = s_atn + w*1024;
    unsigned sb_w = (unsigned)__cvta_generic_to_shared(s_atn_w);

    for (int s = 0; s < 8; s++) {
        // ---- prefetch prologue before sync wait (atn is step-invariant) ----
        if (s < 7) { PREFETCH(0); PREFETCH(1); PREFETCH(2); PREFETCH(3); }

        // ---- for s>0: wait for step s-1 reduction, update locally ----
        if (s > 0) {
            if (tid == 0) {
                while (ldacq(&g_arr[s-1]) < NBS) __nanosleep(64);
            }
            __syncthreads();
            if (tid < 12) s_t[tid] = ldacqf(&g_accP[s-1][tid*32]);
            __syncthreads();
            if (tid == 0) {
                float t[12];
                #pragma unroll
                for (int k = 0; k < 12; k++) t[k] = s_t[k];
                float G0=t[3],G1=t[4],G2=t[5],G3=t[6],G4=t[7],G5=t[8],G6=t[9],G7=t[10],G8=t[11];
                float S10 = Q[1]*G0 + Q[4]*G3 + Q[7]*G6;
                float S01 = Q[0]*G1 + Q[3]*G4 + Q[6]*G7;
                float S20 = Q[2]*G0 + Q[5]*G3 + Q[8]*G6;
                float S02 = Q[0]*G2 + Q[3]*G5 + Q[6]*G8;
                float S21 = Q[2]*G1 + Q[5]*G4 + Q[8]*G7;
                float S12 = Q[1]*G2 + Q[4]*G5 + Q[7]*G8;
                float b10 = S10 - S01, b20 = S20 - S02, b21 = S21 - S12;
                float T10 = b10 / Rm[0];
                float T21 = b21 / Rm[4];
                float T20 = (b20 - T21*Rm[1]) / Rm[0];
                #pragma unroll
                for (int i = 0; i < 3; i++) {
                    pr[i*3+0] -= Q[i*3+1]*T10 + Q[i*3+2]*T20;   // ROT_LR=1
                    pr[i*3+1] -= Q[i*3+2]*T21;
                }
                #pragma unroll
                for (int i = 0; i < 3; i++) trv[i] -= 0.1f * t[i];   // TRANS_LR
                qr3(pr, Q, Rm);
                #pragma unroll
                for (int i = 0; i < 9; i++) s_upd[i] = Q[i];
                #pragma unroll
                for (int i = 0; i < 3; i++) s_upd[9+i] = trv[i];
            }
            __syncthreads();
        }

        // ---- forward ----
        float q0v=s_upd[0],q1v=s_upd[1],q2v=s_upd[2],q3v=s_upd[3],q4v=s_upd[4],
              q5v=s_upd[5],q6v=s_upd[6],q7v=s_upd[7],q8v=s_upd[8];
        float t0=s_upd[9],t1=s_upd[10],t2=s_upd[11];
        float nx0 = q0v*lx0 + q1v*ly0 + q2v*lz0 + t0;
        float ny0 = q3v*lx0 + q4v*ly0 + q5v*lz0 + t1;
        float nz0 = q6v*lx0 + q7v*ly0 + q8v*lz0 + t2;
        float nx1 = q0v*lx1 + q1v*ly1 + q2v*lz1 + t0;
        float ny1 = q3v*lx1 + q4v*ly1 + q5v*lz1 + t1;
        float nz1 = q6v*lx1 + q7v*ly1 + q8v*lz1 + t2;
        if (h == 0 && lane == 0) {
            float* o = out + (size_t)s*3*Lq + 3*l0;
            o[0]=nx0; o[1]=ny0; o[2]=nz0; o[3]=nx1; o[4]=ny1; o[5]=nz1;
        }
        if (s == 7) break;

        u64 X0 = pk2(nx0,nx0), Y0 = pk2(ny0,ny0), Z0 = pk2(nz0,nz0);
        u64 X1 = pk2(nx1,nx1), Y1 = pk2(ny1,ny1), Z1 = pk2(nz1,nz1);
        u64 SW0[2] = {0ull,0ull}, AX0[2] = {0ull,0ull}, AY0[2] = {0ull,0ull}, AZ0[2] = {0ull,0ull};
        u64 SW1[2] = {0ull,0ull}, AX1[2] = {0ull,0ull}, AY1[2] = {0ull,0ull}, AZ1[2] = {0ull,0ull};

        // ---- streamed pair loop: 32 chunks, 4-deep cp.async pipeline,
        //      dual accumulator sets alternating by chunk parity ----
        #pragma unroll 4
        for (int c = 0; c < 28; c++) {
            asm volatile("cp.async.wait_group 3;" ::: "memory");
            CHUNK(c);
            PREFETCH(c + 4);
        }
        asm volatile("cp.async.wait_group 3;" ::: "memory"); CHUNK(28);
        asm volatile("cp.async.wait_group 2;" ::: "memory"); CHUNK(29);
        asm volatile("cp.async.wait_group 1;" ::: "memory"); CHUNK(30);
        asm volatile("cp.async.wait_group 0;" ::: "memory"); CHUNK(31);

        // ---- merge sets, warp reduce -> smem -> block partials -> atomics ----
        float v[8], tA, tB2;
        up2(add2(SW0[0],SW0[1]), tA, tB2); v[0] = tA + tB2;
        up2(add2(AX0[0],AX0[1]), tA, tB2); v[1] = tA + tB2;
        up2(add2(AY0[0],AY0[1]), tA, tB2); v[2] = tA + tB2;
        up2(add2(AZ0[0],AZ0[1]), tA, tB2); v[3] = tA + tB2;
        up2(add2(SW1[0],SW1[1]), tA, tB2); v[4] = tA + tB2;
        up2(add2(AX1[0],AX1[1]), tA, tB2); v[5] = tA + tB2;
        up2(add2(AY1[0],AY1[1]), tA, tB2); v[6] = tA + tB2;
        up2(add2(AZ1[0],AZ1[1]), tA, tB2); v[7] = tA + tB2;
        #pragma unroll
        for (int k = 0; k < 8; k++)
            #pragma unroll
            for (int o = 16; o > 0; o >>= 1)
                v[k] += __shfl_down_sync(0xffffffffu, v[k], o);
        if (lane == 0)
            #pragma unroll
            for (int k = 0; k < 8; k++) s_ws[w][k] = v[k];
        __syncthreads();

        if (tid < 8) {
            int lpi = tid >> 1, sub = tid & 1, off = sub*4;
            float sw = s_ws[lpi][off]     + s_ws[lpi+4][off];
            float ax = s_ws[lpi][off+1]   + s_ws[lpi+4][off+1];
            float ay = s_ws[lpi][off+2]   + s_ws[lpi+4][off+2];
            float az = s_ws[lpi][off+3]   + s_ws[lpi+4][off+3];
            float lx = s_ligc[tid][0], ly = s_ligc[tid][1], lz = s_ligc[tid][2];
            float nx = q0v*lx + q1v*ly + q2v*lz + t0;
            float ny = q3v*lx + q4v*ly + q5v*lz + t1;
            float nz = q6v*lx + q7v*ly + q8v*lz + t2;
            const float Cc = -2.f / 8388608.f;     // -2/(L*R)
            float gx = Cc * (sw*nx + ax);          // ax holds -sum(w*rx)
            float gy = Cc * (sw*ny + ay);
            float gz = Cc * (sw*nz + az);
            s_red12[tid][0]=gx;    s_red12[tid][1]=gy;    s_red12[tid][2]=gz;
            s_red12[tid][3]=gx*lx; s_red12[tid][4]=gx*ly; s_red12[tid][5]=gx*lz;
            s_red12[tid][6]=gy*lx; s_red12[tid][7]=gy*ly; s_red12[tid][8]=gy*lz;
            s_red12[tid][9]=gz*lx; s_red12[tid][10]=gz*ly; s_red12[tid][11]=gz*lz;
        }
        __syncthreads();
        if (tid < 12) {
            float t = 0.f;
            #pragma unroll
            for (int i = 0; i < 8; i++) t += s_red12[i][tid];
            atomicAdd(&g_accP[s][tid*32], t);      // 12 separate 128B lines
        }
        __syncthreads();
        if (tid == 0) {
            __threadfence();
            atomicAdd(&g_arr[s], 1u);
        }
    }
}

extern "C" void kernel_launch(void* const* d_in, const int* in_sizes, int n_in,
                              void* d_out, int out_size) {
    const float* lig_feat  = (const float*)d_in[0];
    const float* rec_feat  = (const float*)d_in[1];
    const float* lig_coord = (const float*)d_in[2];
    const float* rec_coord = (const float*)d_in[3];
    const float* pre_rot   = (const float*)d_in[4];
    const float* trans     = (const float*)d_in[5];
    float* out = (float*)d_out;

    static bool attr_set = false;
    if (!attr_set) {
        cudaFuncSetAttribute(k_steps, cudaFuncAttributeMaxDynamicSharedMemorySize,
                             131072);   // 96KB coords + 32KB atn ring
        attr_set = true;
    }

    k_atn<<<dim3(Rr/64, Lq/64), 256>>>(lig_feat, rec_feat);
    k_steps<<<NBS, NTS, 131072>>>(lig_coord, rec_coord, pre_rot, trans, out);
}

// round 13
// speedup vs baseline: 1.0654x; 1.0654x over previous
#include <cuda_runtime.h>
#include <math.h>
#include <stdint.h>

#define Lq 1024
#define Rr 8192
#define NBS 128
#define NTS 256

typedef unsigned long long u64;

// ---------------- scratch (device globals; no allocs allowed) ----------------
__device__ float g_atn[(size_t)Lq * Rr];     // [l][r] 32MB, L2-resident
__device__ float g_accP[7][12*32];           // per-step grad sums, 128B element stride
__device__ unsigned g_arr[7];                // per-step arrival counters
__device__ unsigned g_cnt;                   // init gridbar counter
__device__ unsigned g_sense;                 // init gridbar sense

__device__ __forceinline__ float frcp(float x) {
    float y; asm("rcp.approx.f32 %0, %1;" : "=f"(y) : "f"(x)); return y;
}
__device__ __forceinline__ u64 pk2(float lo, float hi) {
    u64 r; asm("mov.b64 %0, {%1, %2};" : "=l"(r) : "f"(lo), "f"(hi)); return r;
}
__device__ __forceinline__ void up2(u64 v, float& a, float& b) {
    asm("mov.b64 {%0, %1}, %2;" : "=f"(a), "=f"(b) : "l"(v));
}
__device__ __forceinline__ u64 add2(u64 a, u64 b) {
    u64 d; asm("add.rn.f32x2 %0, %1, %2;" : "=l"(d) : "l"(a), "l"(b)); return d;
}
__device__ __forceinline__ u64 mul2(u64 a, u64 b) {
    u64 d; asm("mul.rn.f32x2 %0, %1, %2;" : "=l"(d) : "l"(a), "l"(b)); return d;
}
__device__ __forceinline__ u64 fma2(u64 a, u64 b, u64 c) {
    u64 d; asm("fma.rn.f32x2 %0, %1, %2, %3;" : "=l"(d) : "l"(a), "l"(b), "l"(c)); return d;
}
__device__ __forceinline__ unsigned ldacq(const unsigned* p) {
    unsigned v; asm volatile("ld.acquire.gpu.u32 %0, [%1];" : "=r"(v) : "l"(p) : "memory"); return v;
}
__device__ __forceinline__ float ldacqf(const float* p) {
    float v; asm volatile("ld.acquire.gpu.f32 %0, [%1];" : "=f"(v) : "l"(p) : "memory"); return v;
}
__device__ __forceinline__ void strel(unsigned* p, unsigned v) {
    asm volatile("st.release.gpu.u32 [%0], %1;" :: "l"(p), "r"(v) : "memory");
}
__device__ __forceinline__ void cpasync16(unsigned dst, const void* src) {
    asm volatile("cp.async.cg.shared.global [%0], [%1], 16;" :: "r"(dst), "l"(src) : "memory");
}

// sense-reversing grid barrier (once at init); self-resetting across replays.
__device__ __forceinline__ void gridbar(unsigned& sense) {
    __syncthreads();
    if (threadIdx.x == 0) {
        unsigned ns = sense ^ 1u;
        __threadfence();
        unsigned old = atomicAdd(&g_cnt, 1u);
        if (old == NBS - 1u) {
            atomicExch(&g_cnt, 0u);
            strel(&g_sense, ns);
        } else {
            while (ldacq(&g_sense) != ns) {}
        }
    }
    __syncthreads();
    sense ^= 1u;
}

// LAPACK-convention Householder QR of a 3x3 (geqrf+orgqr signs).
__device__ void qr3(const float* A, float* Q, float* Rm) {
    float M[9];
    #pragma unroll
    for (int i = 0; i < 9; i++) M[i] = A[i];
    float Qa[9] = {1.f,0.f,0.f, 0.f,1.f,0.f, 0.f,0.f,1.f};
    #pragma unroll
    for (int k = 0; k < 2; k++) {
        float alpha = M[k*3+k];
        float xn2 = 0.f;
        for (int j = k+1; j < 3; j++) xn2 += M[j*3+k]*M[j*3+k];
        if (xn2 == 0.f) continue;
        float nrm  = sqrtf(alpha*alpha + xn2);
        float beta = (alpha >= 0.f) ? -nrm : nrm;
        float v[3] = {0.f,0.f,0.f};
        v[k] = 1.f;
        float denom = alpha - beta;
        for (int j = k+1; j < 3; j++) v[j] = M[j*3+k] / denom;
        float tau = (beta - alpha) / beta;
        for (int c = k; c < 3; c++) {
            float s = 0.f;
            for (int j = k; j < 3; j++) s += v[j]*M[j*3+c];
            s *= tau;
            for (int j = k; j < 3; j++) M[j*3+c] -= s*v[j];
        }
        M[k*3+k] = beta;
        for (int j = k+1; j < 3; j++) M[j*3+k] = 0.f;
        for (int i = 0; i < 3; i++) {
            float s = 0.f;
            for (int j = k; j < 3; j++) s += Qa[i*3+j]*v[j];
            s *= tau;
            for (int j = k; j < 3; j++) Qa[i*3+j] -= s*v[j];
        }
    }
    #pragma unroll
    for (int i = 0; i < 9; i++) { Q[i] = Qa[i]; Rm[i] = M[i]; }
}

__device__ __forceinline__ float blockSum(float v, float* s8) {
    #pragma unroll
    for (int o = 16; o > 0; o >>= 1) v += __shfl_down_sync(0xffffffffu, v, o);
    __syncthreads();
    if ((threadIdx.x & 31) == 0) s8[threadIdx.x >> 5] = v;
    __syncthreads();
    float t = s8[0];
    #pragma unroll
    for (int i = 1; i < 8; i++) t += s8[i];
    return t;
}

// ---------------- atn[l][r] = dot(lig_feat[l], rec_feat[r]) -------------------
// 8l x 4r register tile, 128l x 64r block tile, packed f32x2, XOR swizzle.
// rec rows tx+16i (row-stride-1 swizzle pattern), lig rows ty*8+j (broadcast).
__global__ void __launch_bounds__(256) k_atn(const float* __restrict__ lig_feat,
                                             const float* __restrict__ rec_feat) {
    __shared__ float4 ligs4[128*16];
    __shared__ float4 recs4[64*16];
    int tid = threadIdx.x;
    int tx = tid & 15;       // r-lane
    int ty = tid >> 4;       // l-group (8 rows)
    int r0 = blockIdx.x * 64;
    int l0 = blockIdx.y * 128;
    const float4* ligf4 = (const float4*)lig_feat;
    const float4* recf4 = (const float4*)rec_feat;
    #pragma unroll
    for (int i = 0; i < 8; i++) {
        int idx = i*256 + tid;
        int row = idx >> 4;
        int f4  = idx & 15;
        ligs4[row*16 + (f4 ^ (row & 7))] = ligf4[(size_t)(l0+row)*16 + f4];
    }
    #pragma unroll
    for (int i = 0; i < 4; i++) {
        int idx = i*256 + tid;
        int row = idx >> 4;
        int f4  = idx & 15;
        recs4[row*16 + (f4 ^ (row & 7))] = recf4[(size_t)(r0+row)*16 + f4];
    }
    __syncthreads();

    u64 acc[8][4];
    #pragma unroll
    for (int j = 0; j < 8; j++)
        #pragma unroll
        for (int i = 0; i < 4; i++) acc[j][i] = 0ull;

    #pragma unroll
    for (int f4 = 0; f4 < 16; f4++) {
        ulonglong2 a[4];
        #pragma unroll
        for (int i = 0; i < 4; i++) {
            int row = tx + 16*i;
            a[i] = *(const ulonglong2*)&recs4[row*16 + (f4 ^ (row & 7))];
        }
        #pragma unroll
        for (int j = 0; j < 8; j++) {
            int row = ty*8 + j;
            ulonglong2 bv = *(const ulonglong2*)&ligs4[row*16 + (f4 ^ (row & 7))];
            #pragma unroll
            for (int i = 0; i < 4; i++) {
                acc[j][i] = fma2(a[i].x, bv.x, acc[j][i]);
                acc[j][i] = fma2(a[i].y, bv.y, acc[j][i]);
            }
        }
    }
    #pragma unroll
    for (int j = 0; j < 8; j++) {
        size_t rowbase = (size_t)(l0 + ty*8 + j) * Rr + r0;
        #pragma unroll
        for (int i = 0; i < 4; i++) {
            float lo, hi; up2(acc[j][i], lo, hi);
            g_atn[rowbase + tx + 16*i] = lo + hi;
        }
    }
}

// process one u64 (2 r's) for both l's
#define PAIR_BODY(Av0, Av1, cx, cy, cz)                                         \
    {                                                                           \
        u64 dx = add2(X0, cx), dy = add2(Y0, cy), dz = add2(Z0, cz);            \
        u64 d = mul2(dx, dx); d = fma2(dy, dy, d); d = fma2(dz, dz, d);         \
        float dl, dh; up2(d, dl, dh);                                           \
        u64 inv = pk2(frcp(dl), frcp(dh));                                      \
        u64 i4 = mul2(inv, inv);                                                \
        u64 wv = mul2(Av0, i4);                                                 \
        sw0 = add2(sw0, wv);                                                    \
        ax0 = fma2(wv, cx, ax0); ay0 = fma2(wv, cy, ay0); az0 = fma2(wv, cz, az0); \
        dx = add2(X1, cx); dy = add2(Y1, cy); dz = add2(Z1, cz);                \
        d = mul2(dx, dx); d = fma2(dy, dy, d); d = fma2(dz, dz, d);             \
        up2(d, dl, dh);                                                         \
        inv = pk2(frcp(dl), frcp(dh));                                          \
        i4 = mul2(inv, inv);                                                    \
        wv = mul2(Av1, i4);                                                     \
        sw1 = add2(sw1, wv);                                                    \
        ax1 = fma2(wv, cx, ax1); ay1 = fma2(wv, cy, ay1); az1 = fma2(wv, cz, az1); \
    }

// prefetch chunk c (128 r's) into ring stage (c&3): 2 x 16B per lane
#define PREFETCH(c)                                                             \
    {                                                                           \
        unsigned d0 = sb_w + (((c) & 3)*256 + lane*4)*4;                        \
        cpasync16(d0,       ga0 + (c)*128 + lane*4);                            \
        cpasync16(d0 + 512, ga1 + (c)*128 + lane*4);                            \
        asm volatile("cp.async.commit_group;" ::: "memory");                    \
    }

// compute chunk c from ring stage (c&3): 4 r per lane x 2 l
#define CHUNK(c)                                                                \
    {                                                                           \
        const float4 a0 = *(const float4*)(s_atn_w + ((c) & 3)*256 + lane*4);   \
        const float4 a1 = *(const float4*)(s_atn_w + ((c) & 3)*256 + 128 + lane*4); \
        int idx = (c)*32 + lane;                                                \
        ulonglong2 vx = pX[idx], vy = pY[idx], vz = pZ[idx];                    \
        PAIR_BODY(pk2(a0.x,a0.y), pk2(a1.x,a1.y), vx.x, vy.x, vz.x);            \
        PAIR_BODY(pk2(a0.z,a0.w), pk2(a1.z,a1.w), vx.y, vy.y, vz.y);            \
    }

// ---------------- persistent kernel: preps + all 8 steps ----------------------
__global__ void __launch_bounds__(NTS, 1) k_steps(const float* __restrict__ lig_coord,
                                                  const float* __restrict__ rec_coord,
                                                  const float* __restrict__ pre_rot,
                                                  const float* __restrict__ trans,
                                                  float* __restrict__ out) {
    extern __shared__ float sm[];
    u64* cX = (u64*)sm;                  // [4096] packed r-pairs of (mean - x)
    u64* cY = cX + 4096;
    u64* cZ = cY + 4096;
    float* s_atn = sm + 24576;           // [8 warps][4 stages][2 l][128 r] = 32KB
    __shared__ float s_red[8];
    __shared__ float s_ws[8][8];
    __shared__ float s_red12[8][12];
    __shared__ float s_ligc[8][3];
    __shared__ float s_upd[12];          // current-step Q(9)+tr(3)
    __shared__ float s_t[12];            // fetched global gradient sums

    int tid = threadIdx.x, b = blockIdx.x;
    int w = tid >> 5, lane = tid & 31;
    int lp = w & 3, h = w >> 2;                // l-pair idx (0..3), r-half (0..1)
    int l0 = b*8 + lp*2;                       // warp handles l0, l0+1

    unsigned sense;
    { volatile unsigned* gs = &g_sense; sense = *gs; }

    // ---- rec means ----
    float sx = 0.f, sy = 0.f, sz = 0.f;
    for (int i = tid; i < Rr; i += NTS) {
        sx += rec_coord[3*i]; sy += rec_coord[3*i+1]; sz += rec_coord[3*i+2];
    }
    float mx = blockSum(sx, s_red) * (1.f/Rr);
    float my = blockSum(sy, s_red) * (1.f/Rr);
    float mz = blockSum(sz, s_red) * (1.f/Rr);

    // ---- build negated-centered coord arrays (4 r's per thread-iter) ----
    {
        const float4* rc4 = (const float4*)rec_coord;
        ulonglong2* vX = (ulonglong2*)cX;
        ulonglong2* vY = (ulonglong2*)cY;
        ulonglong2* vZ = (ulonglong2*)cZ;
        for (int p4 = tid; p4 < Rr/4; p4 += NTS) {
            float4 f0 = rc4[3*p4], f1 = rc4[3*p4+1], f2 = rc4[3*p4+2];
            ulonglong2 ox, oy, oz;
            ox.x = pk2(mx - f0.x, mx - f0.w);
            ox.y = pk2(mx - f1.z, mx - f2.y);
            oy.x = pk2(my - f0.y, my - f1.x);
            oy.y = pk2(my - f1.w, my - f2.z);
            oz.x = pk2(mz - f0.z, mz - f1.y);
            oz.y = pk2(mz - f2.x, mz - f2.w);
            vX[p4] = ox; vY[p4] = oy; vZ[p4] = oz;
        }
    }

    // ---- lig means + centered coords for this block's 8 l's ----
    float lsx = 0.f, lsy = 0.f, lsz = 0.f;
    for (int i = tid; i < Lq; i += NTS) {
        lsx += lig_coord[3*i]; lsy += lig_coord[3*i+1]; lsz += lig_coord[3*i+2];
    }
    float mlx = blockSum(lsx, s_red) * (1.f/Lq);
    float mly = blockSum(lsy, s_red) * (1.f/Lq);
    float mlz = blockSum(lsz, s_red) * (1.f/Lq);
    if (tid < 8) {
        int l = b*8 + tid;
        s_ligc[tid][0] = lig_coord[3*l]   - mlx;
        s_ligc[tid][1] = lig_coord[3*l+1] - mly;
        s_ligc[tid][2] = lig_coord[3*l+2] - mlz;
    }

    // ---- per-block optimizer state (identical in every block: deterministic) ----
    float pr[9], trv[3], Q[9], Rm[9];
    if (tid == 0) {
        #pragma unroll
        for (int i = 0; i < 9; i++) pr[i] = pre_rot[i];
        #pragma unroll
        for (int i = 0; i < 3; i++) trv[i] = trans[i] * 4.0f;   // TRANS_DIST
        qr3(pr, Q, Rm);
        #pragma unroll
        for (int i = 0; i < 9; i++) s_upd[i] = Q[i];
        #pragma unroll
        for (int i = 0; i < 3; i++) s_upd[9+i] = trv[i];
    }

    // ---- block 0 zeroes the per-step accumulators/counters ----
    if (b == 0) {
        for (int i = tid; i < 7*12*32; i += NTS) ((float*)g_accP)[i] = 0.f;
        if (tid < 7) g_arr[tid] = 0u;
    }
    gridbar(sense);   // accumulators zeroed + smem coords/params ready

    float lx0 = s_ligc[lp*2][0],   ly0 = s_ligc[lp*2][1],   lz0 = s_ligc[lp*2][2];
    float lx1 = s_ligc[lp*2+1][0], ly1 = s_ligc[lp*2+1][1], lz1 = s_ligc[lp*2+1][2];

    const float* ga0 = g_atn + (size_t)l0*Rr     + h*4096;
    const float* ga1 = g_atn + (size_t)(l0+1)*Rr + h*4096;
    const ulonglong2* pX = (const ulonglong2*)cX + h*1024;
    const ulonglong2* pY = (const ulonglong2*)cY + h*1024;
    const ulonglong2* pZ = (const ulonglong2*)cZ + h*1024;
    const float* s_atn_w = s_atn + w*1024;
    unsigned sb_w = (unsigned)__cvta_generic_to_shared(s_atn_w);

    for (int s = 0; s < 8; s++) {
        // ---- prefetch prologue before sync wait (atn is step-invariant) ----
        if (s < 7) { PREFETCH(0); PREFETCH(1); PREFETCH(2); PREFETCH(3); }

        // ---- for s>0: wait for step s-1 reduction, update locally ----
        if (s > 0) {
            if (tid == 0) {
                while (ldacq(&g_arr[s-1]) < NBS) __nanosleep(64);
            }
            __syncthreads();
            if (tid < 12) s_t[tid] = ldacqf(&g_accP[s-1][tid*32]);
            __syncthreads();
            if (tid == 0) {
                float t[12];
                #pragma unroll
                for (int k = 0; k < 12; k++) t[k] = s_t[k];
                float G0=t[3],G1=t[4],G2=t[5],G3=t[6],G4=t[7],G5=t[8],G6=t[9],G7=t[10],G8=t[11];
                float S10 = Q[1]*G0 + Q[4]*G3 + Q[7]*G6;
                float S01 = Q[0]*G1 + Q[3]*G4 + Q[6]*G7;
                float S20 = Q[2]*G0 + Q[5]*G3 + Q[8]*G6;
                float S02 = Q[0]*G2 + Q[3]*G5 + Q[6]*G8;
                float S21 = Q[2]*G1 + Q[5]*G4 + Q[8]*G7;
                float S12 = Q[1]*G2 + Q[4]*G5 + Q[7]*G8;
                float b10 = S10 - S01, b20 = S20 - S02, b21 = S21 - S12;
                float T10 = b10 / Rm[0];
                float T21 = b21 / Rm[4];
                float T20 = (b20 - T21*Rm[1]) / Rm[0];
                #pragma unroll
                for (int i = 0; i < 3; i++) {
                    pr[i*3+0] -= Q[i*3+1]*T10 + Q[i*3+2]*T20;   // ROT_LR=1
                    pr[i*3+1] -= Q[i*3+2]*T21;
                }
                #pragma unroll
                for (int i = 0; i < 3; i++) trv[i] -= 0.1f * t[i];   // TRANS_LR
                qr3(pr, Q, Rm);
                #pragma unroll
                for (int i = 0; i < 9; i++) s_upd[i] = Q[i];
                #pragma unroll
                for (int i = 0; i < 3; i++) s_upd[9+i] = trv[i];
            }
            __syncthreads();
        }

        // ---- forward ----
        float q0v=s_upd[0],q1v=s_upd[1],q2v=s_upd[2],q3v=s_upd[3],q4v=s_upd[4],
              q5v=s_upd[5],q6v=s_upd[6],q7v=s_upd[7],q8v=s_upd[8];
        float t0=s_upd[9],t1=s_upd[10],t2=s_upd[11];
        float nx0 = q0v*lx0 + q1v*ly0 + q2v*lz0 + t0;
        float ny0 = q3v*lx0 + q4v*ly0 + q5v*lz0 + t1;
        float nz0 = q6v*lx0 + q7v*ly0 + q8v*lz0 + t2;
        float nx1 = q0v*lx1 + q1v*ly1 + q2v*lz1 + t0;
        float ny1 = q3v*lx1 + q4v*ly1 + q5v*lz1 + t1;
        float nz1 = q6v*lx1 + q7v*ly1 + q8v*lz1 + t2;
        if (h == 0 && lane == 0) {
            float* o = out + (size_t)s*3*Lq + 3*l0;
            o[0]=nx0; o[1]=ny0; o[2]=nz0; o[3]=nx1; o[4]=ny1; o[5]=nz1;
        }
        if (s == 7) break;

        u64 X0 = pk2(nx0,nx0), Y0 = pk2(ny0,ny0), Z0 = pk2(nz0,nz0);
        u64 X1 = pk2(nx1,nx1), Y1 = pk2(ny1,ny1), Z1 = pk2(nz1,nz1);
        u64 sw0 = 0ull, ax0 = 0ull, ay0 = 0ull, az0 = 0ull;
        u64 sw1 = 0ull, ax1 = 0ull, ay1 = 0ull, az1 = 0ull;

        // ---- streamed pair loop: 32 chunks, 4-deep cp.async pipeline ----
        #pragma unroll 4
        for (int c = 0; c < 28; c++) {
            asm volatile("cp.async.wait_group 3;" ::: "memory");
            CHUNK(c);
            PREFETCH(c + 4);
        }
        asm volatile("cp.async.wait_group 3;" ::: "memory"); CHUNK(28);
        asm volatile("cp.async.wait_group 2;" ::: "memory"); CHUNK(29);
        asm volatile("cp.async.wait_group 1;" ::: "memory"); CHUNK(30);
        asm volatile("cp.async.wait_group 0;" ::: "memory"); CHUNK(31);

        // ---- warp reduce -> smem -> block partials -> spread global atomics ----
        float v[8], tA, tB2;
        up2(sw0, tA, tB2); v[0] = tA + tB2;
        up2(ax0, tA, tB2); v[1] = tA + tB2;
        up2(ay0, tA, tB2); v[2] = tA + tB2;
        up2(az0, tA, tB2); v[3] = tA + tB2;
        up2(sw1, tA, tB2); v[4] = tA + tB2;
        up2(ax1, tA, tB2); v[5] = tA + tB2;
        up2(ay1, tA, tB2); v[6] = tA + tB2;
        up2(az1, tA, tB2); v[7] = tA + tB2;
        #pragma unroll
        for (int k = 0; k < 8; k++)
            #pragma unroll
            for (int o = 16; o > 0; o >>= 1)
                v[k] += __shfl_down_sync(0xffffffffu, v[k], o);
        if (lane == 0)
            #pragma unroll
            for (int k = 0; k < 8; k++) s_ws[w][k] = v[k];
        __syncthreads();

        if (tid < 8) {
            int lpi = tid >> 1, sub = tid & 1, off = sub*4;
            float sw = s_ws[lpi][off]     + s_ws[lpi+4][off];
            float ax = s_ws[lpi][off+1]   + s_ws[lpi+4][off+1];
            float ay = s_ws[lpi][off+2]   + s_ws[lpi+4][off+2];
            float az = s_ws[lpi][off+3]   + s_ws[lpi+4][off+3];
            float lx = s_ligc[tid][0], ly = s_ligc[tid][1], lz = s_ligc[tid][2];
            float nx = q0v*lx + q1v*ly + q2v*lz + t0;
            float ny = q3v*lx + q4v*ly + q5v*lz + t1;
            float nz = q6v*lx + q7v*ly + q8v*lz + t2;
            const float Cc = -2.f / 8388608.f;     // -2/(L*R)
            float gx = Cc * (sw*nx + ax);          // ax holds -sum(w*rx)
            float gy = Cc * (sw*ny + ay);
            float gz = Cc * (sw*nz + az);
            s_red12[tid][0]=gx;    s_red12[tid][1]=gy;    s_red12[tid][2]=gz;
            s_red12[tid][3]=gx*lx; s_red12[tid][4]=gx*ly; s_red12[tid][5]=gx*lz;
            s_red12[tid][6]=gy*lx; s_red12[tid][7]=gy*ly; s_red12[tid][8]=gy*lz;
            s_red12[tid][9]=gz*lx; s_red12[tid][10]=gz*ly; s_red12[tid][11]=gz*lz;
        }
        __syncthreads();
        if (tid < 12) {
            float t = 0.f;
            #pragma unroll
            for (int i = 0; i < 8; i++) t += s_red12[i][tid];
            atomicAdd(&g_accP[s][tid*32], t);      // 12 separate 128B lines
        }
        __syncthreads();
        if (tid == 0) {
            __threadfence();
            atomicAdd(&g_arr[s], 1u);
        }
    }
}

extern "C" void kernel_launch(void* const* d_in, const int* in_sizes, int n_in,
                              void* d_out, int out_size) {
    const float* lig_feat  = (const float*)d_in[0];
    const float* rec_feat  = (const float*)d_in[1];
    const float* lig_coord = (const float*)d_in[2];
    const float* rec_coord = (const float*)d_in[3];
    const float* pre_rot   = (const float*)d_in[4];
    const float* trans     = (const float*)d_in[5];
    float* out = (float*)d_out;

    static bool attr_set = false;
    if (!attr_set) {
        cudaFuncSetAttribute(k_steps, cudaFuncAttributeMaxDynamicSharedMemorySize,
                             131072);   // 96KB coords + 32KB atn ring
        attr_set = true;
    }

    k_atn<<<dim3(Rr/64, Lq/128), 256>>>(lig_feat, rec_feat);
    k_steps<<<NBS, NTS, 131072>>>(lig_coord, rec_coord, pre_rot, trans, out);
}

// round 14
// speedup vs baseline: 1.0956x; 1.0283x over previous
#include <cuda_runtime.h>
#include <math.h>
#include <stdint.h>

#define Lq 1024
#define Rr 8192
#define NBS 128
#define NTS 256

typedef unsigned long long u64;

// ---------------- scratch (device globals; no allocs allowed) ----------------
__device__ float g_atn[(size_t)Lq * Rr];     // [l][r] 32MB, L2-resident
__device__ float g_accP[7][12*32];           // per-step grad sums, 128B element stride
__device__ unsigned g_arr[7];                // per-step arrival counters
__device__ unsigned g_cnt;                   // init gridbar counter
__device__ unsigned g_sense;                 // init gridbar sense

__device__ __forceinline__ float frcp(float x) {
    float y; asm("rcp.approx.f32 %0, %1;" : "=f"(y) : "f"(x)); return y;
}
__device__ __forceinline__ u64 pk2(float lo, float hi) {
    u64 r; asm("mov.b64 %0, {%1, %2};" : "=l"(r) : "f"(lo), "f"(hi)); return r;
}
__device__ __forceinline__ void up2(u64 v, float& a, float& b) {
    asm("mov.b64 {%0, %1}, %2;" : "=f"(a), "=f"(b) : "l"(v));
}
__device__ __forceinline__ u64 add2(u64 a, u64 b) {
    u64 d; asm("add.rn.f32x2 %0, %1, %2;" : "=l"(d) : "l"(a), "l"(b)); return d;
}
__device__ __forceinline__ u64 mul2(u64 a, u64 b) {
    u64 d; asm("mul.rn.f32x2 %0, %1, %2;" : "=l"(d) : "l"(a), "l"(b)); return d;
}
__device__ __forceinline__ u64 fma2(u64 a, u64 b, u64 c) {
    u64 d; asm("fma.rn.f32x2 %0, %1, %2, %3;" : "=l"(d) : "l"(a), "l"(b), "l"(c)); return d;
}
__device__ __forceinline__ unsigned ldacq(const unsigned* p) {
    unsigned v; asm volatile("ld.acquire.gpu.u32 %0, [%1];" : "=r"(v) : "l"(p) : "memory"); return v;
}
__device__ __forceinline__ float ldacqf(const float* p) {
    float v; asm volatile("ld.acquire.gpu.f32 %0, [%1];" : "=f"(v) : "l"(p) : "memory"); return v;
}
__device__ __forceinline__ void strel(unsigned* p, unsigned v) {
    asm volatile("st.release.gpu.u32 [%0], %1;" :: "l"(p), "r"(v) : "memory");
}
__device__ __forceinline__ void cpasync16(unsigned dst, const void* src) {
    asm volatile("cp.async.cg.shared.global [%0], [%1], 16;" :: "r"(dst), "l"(src) : "memory");
}

// sense-reversing grid barrier (once at init); self-resetting across replays.
__device__ __forceinline__ void gridbar(unsigned& sense) {
    __syncthreads();
    if (threadIdx.x == 0) {
        unsigned ns = sense ^ 1u;
        __threadfence();
        unsigned old = atomicAdd(&g_cnt, 1u);
        if (old == NBS - 1u) {
            atomicExch(&g_cnt, 0u);
            strel(&g_sense, ns);
        } else {
            while (ldacq(&g_sense) != ns) {}
        }
    }
    __syncthreads();
    sense ^= 1u;
}

// LAPACK-convention Householder QR of a 3x3 (geqrf+orgqr signs).
__device__ void qr3(const float* A, float* Q, float* Rm) {
    float M[9];
    #pragma unroll
    for (int i = 0; i < 9; i++) M[i] = A[i];
    float Qa[9] = {1.f,0.f,0.f, 0.f,1.f,0.f, 0.f,0.f,1.f};
    #pragma unroll
    for (int k = 0; k < 2; k++) {
        float alpha = M[k*3+k];
        float xn2 = 0.f;
        for (int j = k+1; j < 3; j++) xn2 += M[j*3+k]*M[j*3+k];
        if (xn2 == 0.f) continue;
        float nrm  = sqrtf(alpha*alpha + xn2);
        float beta = (alpha >= 0.f) ? -nrm : nrm;
        float v[3] = {0.f,0.f,0.f};
        v[k] = 1.f;
        float denom = alpha - beta;
        for (int j = k+1; j < 3; j++) v[j] = M[j*3+k] / denom;
        float tau = (beta - alpha) / beta;
        for (int c = k; c < 3; c++) {
            float s = 0.f;
            for (int j = k; j < 3; j++) s += v[j]*M[j*3+c];
            s *= tau;
            for (int j = k; j < 3; j++) M[j*3+c] -= s*v[j];
        }
        M[k*3+k] = beta;
        for (int j = k+1; j < 3; j++) M[j*3+k] = 0.f;
        for (int i = 0; i < 3; i++) {
            float s = 0.f;
            for (int j = k; j < 3; j++) s += Qa[i*3+j]*v[j];
            s *= tau;
            for (int j = k; j < 3; j++) Qa[i*3+j] -= s*v[j];
        }
    }
    #pragma unroll
    for (int i = 0; i < 9; i++) { Q[i] = Qa[i]; Rm[i] = M[i]; }
}

__device__ __forceinline__ float blockSum(float v, float* s8) {
    #pragma unroll
    for (int o = 16; o > 0; o >>= 1) v += __shfl_down_sync(0xffffffffu, v, o);
    __syncthreads();
    if ((threadIdx.x & 31) == 0) s8[threadIdx.x >> 5] = v;
    __syncthreads();
    float t = s8[0];
    #pragma unroll
    for (int i = 1; i < 8; i++) t += s8[i];
    return t;
}

// ---------------- atn[l][r] = dot(lig_feat[l], rec_feat[r]) -------------------
// (R13 proven) 8l x 4r register tile, 128l x 64r block tile, packed f32x2.
__global__ void __launch_bounds__(256) k_atn(const float* __restrict__ lig_feat,
                                             const float* __restrict__ rec_feat) {
    __shared__ float4 ligs4[128*16];
    __shared__ float4 recs4[64*16];
    int tid = threadIdx.x;
    int tx = tid & 15;       // r-lane
    int ty = tid >> 4;       // l-group (8 rows)
    int r0 = blockIdx.x * 64;
    int l0 = blockIdx.y * 128;
    const float4* ligf4 = (const float4*)lig_feat;
    const float4* recf4 = (const float4*)rec_feat;
    #pragma unroll
    for (int i = 0; i < 8; i++) {
        int idx = i*256 + tid;
        int row = idx >> 4;
        int f4  = idx & 15;
        ligs4[row*16 + (f4 ^ (row & 7))] = ligf4[(size_t)(l0+row)*16 + f4];
    }
    #pragma unroll
    for (int i = 0; i < 4; i++) {
        int idx = i*256 + tid;
        int row = idx >> 4;
        int f4  = idx & 15;
        recs4[row*16 + (f4 ^ (row & 7))] = recf4[(size_t)(r0+row)*16 + f4];
    }
    __syncthreads();

    u64 acc[8][4];
    #pragma unroll
    for (int j = 0; j < 8; j++)
        #pragma unroll
        for (int i = 0; i < 4; i++) acc[j][i] = 0ull;

    #pragma unroll
    for (int f4 = 0; f4 < 16; f4++) {
        ulonglong2 a[4];
        #pragma unroll
        for (int i = 0; i < 4; i++) {
            int row = tx + 16*i;
            a[i] = *(const ulonglong2*)&recs4[row*16 + (f4 ^ (row & 7))];
        }
        #pragma unroll
        for (int j = 0; j < 8; j++) {
            int row = ty*8 + j;
            ulonglong2 bv = *(const ulonglong2*)&ligs4[row*16 + (f4 ^ (row & 7))];
            #pragma unroll
            for (int i = 0; i < 4; i++) {
                acc[j][i] = fma2(a[i].x, bv.x, acc[j][i]);
                acc[j][i] = fma2(a[i].y, bv.y, acc[j][i]);
            }
        }
    }
    #pragma unroll
    for (int j = 0; j < 8; j++) {
        size_t rowbase = (size_t)(l0 + ty*8 + j) * Rr + r0;
        #pragma unroll
        for (int i = 0; i < 4; i++) {
            float lo, hi; up2(acc[j][i], lo, hi);
            g_atn[rowbase + tx + 16*i] = lo + hi;
        }
    }
}

// expansion form: d2 = (K + |nl|^2) + cx*nx + cy*ny + cz*nz, with c = -2*rc.
// paired reciprocal: 1 MUFU per 2 r's.
#define PAIR_BODY(Av0, Av1, cx, cy, cz, kk)                                     \
    {                                                                           \
        u64 d = add2(kk, B0);                                                   \
        d = fma2(cz, Z0, d); d = fma2(cy, Y0, d); d = fma2(cx, X0, d);          \
        float dl, dh; up2(d, dl, dh);                                           \
        float rp = frcp(dl*dh);                                                 \
        u64 inv = pk2(dh*rp, dl*rp);                                            \
        u64 i4 = mul2(inv, inv);                                                \
        u64 wv = mul2(Av0, i4);                                                 \
        sw0 = add2(sw0, wv);                                                    \
        ax0 = fma2(wv, cx, ax0); ay0 = fma2(wv, cy, ay0); az0 = fma2(wv, cz, az0); \
        d = add2(kk, B1);                                                       \
        d = fma2(cz, Z1, d); d = fma2(cy, Y1, d); d = fma2(cx, X1, d);          \
        up2(d, dl, dh);                                                         \
        rp = frcp(dl*dh);                                                       \
        inv = pk2(dh*rp, dl*rp);                                                \
        i4 = mul2(inv, inv);                                                    \
        wv = mul2(Av1, i4);                                                     \
        sw1 = add2(sw1, wv);                                                    \
        ax1 = fma2(wv, cx, ax1); ay1 = fma2(wv, cy, ay1); az1 = fma2(wv, cz, az1); \
    }

// prefetch chunk c (128 r's) into ring stage (c&3): 2 x 16B per lane
#define PREFETCH(c)                                                             \
    {                                                                           \
        unsigned d0 = sb_w + (((c) & 3)*256 + lane*4)*4;                        \
        cpasync16(d0,       ga0 + (c)*128 + lane*4);                            \
        cpasync16(d0 + 512, ga1 + (c)*128 + lane*4);                            \
        asm volatile("cp.async.commit_group;" ::: "memory");                    \
    }

// compute chunk c from ring stage (c&3): 4 r per lane x 2 l
#define CHUNK(c)                                                                \
    {                                                                           \
        const float4 a0 = *(const float4*)(s_atn_w + ((c) & 3)*256 + lane*4);   \
        const float4 a1 = *(const float4*)(s_atn_w + ((c) & 3)*256 + 128 + lane*4); \
        int idx = (c)*32 + lane;                                                \
        ulonglong2 vx = pX[idx], vy = pY[idx], vz = pZ[idx], vk = pK[idx];      \
        PAIR_BODY(pk2(a0.x,a0.y), pk2(a1.x,a1.y), vx.x, vy.x, vz.x, vk.x);      \
        PAIR_BODY(pk2(a0.z,a0.w), pk2(a1.z,a1.w), vx.y, vy.y, vz.y, vk.y);      \
    }

// ---------------- persistent kernel: preps + all 8 steps ----------------------
__global__ void __launch_bounds__(NTS, 1) k_steps(const float* __restrict__ lig_coord,
                                                  const float* __restrict__ rec_coord,
                                                  const float* __restrict__ pre_rot,
                                                  const float* __restrict__ trans,
                                                  float* __restrict__ out) {
    extern __shared__ float sm[];
    u64* cX = (u64*)sm;                  // [4096] packed r-pairs of -2*(x - mx)
    u64* cY = cX + 4096;
    u64* cZ = cY + 4096;
    u64* cK = cZ + 4096;                 // [4096] packed |rc|^2
    float* s_atn = sm + 32768;           // [8 warps][4 stages][2 l][128 r] = 32KB
    __shared__ float s_red[8];
    __shared__ float s_ws[8][8];
    __shared__ float s_red12[8][12];
    __shared__ float s_ligc[8][3];
    __shared__ float s_upd[12];          // current-step Q(9)+tr(3)
    __shared__ float s_t[12];            // fetched global gradient sums

    int tid = threadIdx.x, b = blockIdx.x;
    int w = tid >> 5, lane = tid & 31;
    int lp = w & 3, h = w >> 2;                // l-pair idx (0..3), r-half (0..1)
    int l0 = b*8 + lp*2;                       // warp handles l0, l0+1

    unsigned sense;
    { volatile unsigned* gs = &g_sense; sense = *gs; }

    // ---- rec means ----
    float sx = 0.f, sy = 0.f, sz = 0.f;
    for (int i = tid; i < Rr; i += NTS) {
        sx += rec_coord[3*i]; sy += rec_coord[3*i+1]; sz += rec_coord[3*i+2];
    }
    float mx = blockSum(sx, s_red) * (1.f/Rr);
    float my = blockSum(sy, s_red) * (1.f/Rr);
    float mz = blockSum(sz, s_red) * (1.f/Rr);

    // ---- build -2*centered coords + |rc|^2 (4 r's per thread-iter) ----
    {
        const float4* rc4 = (const float4*)rec_coord;
        ulonglong2* vX = (ulonglong2*)cX;
        ulonglong2* vY = (ulonglong2*)cY;
        ulonglong2* vZ = (ulonglong2*)cZ;
        ulonglong2* vK = (ulonglong2*)cK;
        for (int p4 = tid; p4 < Rr/4; p4 += NTS) {
            float4 f0 = rc4[3*p4], f1 = rc4[3*p4+1], f2 = rc4[3*p4+2];
            float x0 = f0.x - mx, y0 = f0.y - my, z0 = f0.z - mz;
            float x1 = f0.w - mx, y1 = f1.x - my, z1 = f1.y - mz;
            float x2 = f1.z - mx, y2 = f1.w - my, z2 = f2.x - mz;
            float x3 = f2.y - mx, y3 = f2.z - my, z3 = f2.w - mz;
            float k0 = x0*x0 + y0*y0 + z0*z0;
            float k1 = x1*x1 + y1*y1 + z1*z1;
            float k2 = x2*x2 + y2*y2 + z2*z2;
            float k3 = x3*x3 + y3*y3 + z3*z3;
            ulonglong2 ox, oy, oz, ok;
            ox.x = pk2(-2.f*x0, -2.f*x1); ox.y = pk2(-2.f*x2, -2.f*x3);
            oy.x = pk2(-2.f*y0, -2.f*y1); oy.y = pk2(-2.f*y2, -2.f*y3);
            oz.x = pk2(-2.f*z0, -2.f*z1); oz.y = pk2(-2.f*z2, -2.f*z3);
            ok.x = pk2(k0, k1);           ok.y = pk2(k2, k3);
            vX[p4] = ox; vY[p4] = oy; vZ[p4] = oz; vK[p4] = ok;
        }
    }

    // ---- lig means + centered coords for this block's 8 l's ----
    float lsx = 0.f, lsy = 0.f, lsz = 0.f;
    for (int i = tid; i < Lq; i += NTS) {
        lsx += lig_coord[3*i]; lsy += lig_coord[3*i+1]; lsz += lig_coord[3*i+2];
    }
    float mlx = blockSum(lsx, s_red) * (1.f/Lq);
    float mly = blockSum(lsy, s_red) * (1.f/Lq);
    float mlz = blockSum(lsz, s_red) * (1.f/Lq);
    if (tid < 8) {
        int l = b*8 + tid;
        s_ligc[tid][0] = lig_coord[3*l]   - mlx;
        s_ligc[tid][1] = lig_coord[3*l+1] - mly;
        s_ligc[tid][2] = lig_coord[3*l+2] - mlz;
    }

    // ---- per-block optimizer state (identical in every block: deterministic) ----
    float pr[9], trv[3], Q[9], Rm[9];
    if (tid == 0) {
        #pragma unroll
        for (int i = 0; i < 9; i++) pr[i] = pre_rot[i];
        #pragma unroll
        for (int i = 0; i < 3; i++) trv[i] = trans[i] * 4.0f;   // TRANS_DIST
        qr3(pr, Q, Rm);
        #pragma unroll
        for (int i = 0; i < 9; i++) s_upd[i] = Q[i];
        #pragma unroll
        for (int i = 0; i < 3; i++) s_upd[9+i] = trv[i];
    }

    // ---- block 0 zeroes the per-step accumulators/counters ----
    if (b == 0) {
        for (int i = tid; i < 7*12*32; i += NTS) ((float*)g_accP)[i] = 0.f;
        if (tid < 7) g_arr[tid] = 0u;
    }
    gridbar(sense);   // accumulators zeroed + smem coords/params ready

    float lx0 = s_ligc[lp*2][0],   ly0 = s_ligc[lp*2][1],   lz0 = s_ligc[lp*2][2];
    float lx1 = s_ligc[lp*2+1][0], ly1 = s_ligc[lp*2+1][1], lz1 = s_ligc[lp*2+1][2];

    const float* ga0 = g_atn + (size_t)l0*Rr     + h*4096;
    const float* ga1 = g_atn + (size_t)(l0+1)*Rr + h*4096;
    const ulonglong2* pX = (const ulonglong2*)cX + h*1024;
    const ulonglong2* pY = (const ulonglong2*)cY + h*1024;
    const ulonglong2* pZ = (const ulonglong2*)cZ + h*1024;
    const ulonglong2* pK = (const ulonglong2*)cK + h*1024;
    const float* s_atn_w = s_atn + w*1024;
    unsigned sb_w = (unsigned)__cvta_generic_to_shared(s_atn_w);

    for (int s = 0; s < 8; s++) {
        // ---- prefetch prologue before sync wait (atn is step-invariant) ----
        if (s < 7) { PREFETCH(0); PREFETCH(1); PREFETCH(2); PREFETCH(3); }

        // ---- for s>0: wait for step s-1 reduction, update locally ----
        if (s > 0) {
            if (tid == 0) {
                while (ldacq(&g_arr[s-1]) < NBS) __nanosleep(64);
            }
            __syncthreads();
            if (tid < 12) s_t[tid] = ldacqf(&g_accP[s-1][tid*32]);
            __syncthreads();
            if (tid == 0) {
                float t[12];
                #pragma unroll
                for (int k = 0; k < 12; k++) t[k] = s_t[k];
                float G0=t[3],G1=t[4],G2=t[5],G3=t[6],G4=t[7],G5=t[8],G6=t[9],G7=t[10],G8=t[11];
                float S10 = Q[1]*G0 + Q[4]*G3 + Q[7]*G6;
                float S01 = Q[0]*G1 + Q[3]*G4 + Q[6]*G7;
                float S20 = Q[2]*G0 + Q[5]*G3 + Q[8]*G6;
                float S02 = Q[0]*G2 + Q[3]*G5 + Q[6]*G8;
                float S21 = Q[2]*G1 + Q[5]*G4 + Q[8]*G7;
                float S12 = Q[1]*G2 + Q[4]*G5 + Q[7]*G8;
                float b10 = S10 - S01, b20 = S20 - S02, b21 = S21 - S12;
                float T10 = b10 / Rm[0];
                float T21 = b21 / Rm[4];
                float T20 = (b20 - T21*Rm[1]) / Rm[0];
                #pragma unroll
                for (int i = 0; i < 3; i++) {
                    pr[i*3+0] -= Q[i*3+1]*T10 + Q[i*3+2]*T20;   // ROT_LR=1
                    pr[i*3+1] -= Q[i*3+2]*T21;
                }
                #pragma unroll
                for (int i = 0; i < 3; i++) trv[i] -= 0.1f * t[i];   // TRANS_LR
                qr3(pr, Q, Rm);
                #pragma unroll
                for (int i = 0; i < 9; i++) s_upd[i] = Q[i];
                #pragma unroll
                for (int i = 0; i < 3; i++) s_upd[9+i] = trv[i];
            }
            __syncthreads();
        }

        // ---- forward ----
        float q0v=s_upd[0],q1v=s_upd[1],q2v=s_upd[2],q3v=s_upd[3],q4v=s_upd[4],
              q5v=s_upd[5],q6v=s_upd[6],q7v=s_upd[7],q8v=s_upd[8];
        float t0=s_upd[9],t1=s_upd[10],t2=s_upd[11];
        float nx0 = q0v*lx0 + q1v*ly0 + q2v*lz0 + t0;
        float ny0 = q3v*lx0 + q4v*ly0 + q5v*lz0 + t1;
        float nz0 = q6v*lx0 + q7v*ly0 + q8v*lz0 + t2;
        float nx1 = q0v*lx1 + q1v*ly1 + q2v*lz1 + t0;
        float ny1 = q3v*lx1 + q4v*ly1 + q5v*lz1 + t1;
        float nz1 = q6v*lx1 + q7v*ly1 + q8v*lz1 + t2;
        if (h == 0 && lane == 0) {
            float* o = out + (size_t)s*3*Lq + 3*l0;
            o[0]=nx0; o[1]=ny0; o[2]=nz0; o[3]=nx1; o[4]=ny1; o[5]=nz1;
        }
        if (s == 7) break;

        u64 X0 = pk2(nx0,nx0), Y0 = pk2(ny0,ny0), Z0 = pk2(nz0,nz0);
        u64 X1 = pk2(nx1,nx1), Y1 = pk2(ny1,ny1), Z1 = pk2(nz1,nz1);
        float b0f = nx0*nx0 + ny0*ny0 + nz0*nz0;
        float b1f = nx1*nx1 + ny1*ny1 + nz1*nz1;
        u64 B0 = pk2(b0f,b0f), B1 = pk2(b1f,b1f);
        u64 sw0 = 0ull, ax0 = 0ull, ay0 = 0ull, az0 = 0ull;
        u64 sw1 = 0ull, ax1 = 0ull, ay1 = 0ull, az1 = 0ull;

        // ---- streamed pair loop: 32 chunks, 4-deep cp.async pipeline ----
        #pragma unroll 4
        for (int c = 0; c < 28; c++) {
            asm volatile("cp.async.wait_group 3;" ::: "memory");
            CHUNK(c);
            PREFETCH(c + 4);
        }
        asm volatile("cp.async.wait_group 3;" ::: "memory"); CHUNK(28);
        asm volatile("cp.async.wait_group 2;" ::: "memory"); CHUNK(29);
        asm volatile("cp.async.wait_group 1;" ::: "memory"); CHUNK(30);
        asm volatile("cp.async.wait_group 0;" ::: "memory"); CHUNK(31);

        // ---- warp reduce -> smem -> block partials -> spread global atomics ----
        float v[8], tA, tB2;
        up2(sw0, tA, tB2); v[0] = tA + tB2;
        up2(ax0, tA, tB2); v[1] = tA + tB2;
        up2(ay0, tA, tB2); v[2] = tA + tB2;
        up2(az0, tA, tB2); v[3] = tA + tB2;
        up2(sw1, tA, tB2); v[4] = tA + tB2;
        up2(ax1, tA, tB2); v[5] = tA + tB2;
        up2(ay1, tA, tB2); v[6] = tA + tB2;
        up2(az1, tA, tB2); v[7] = tA + tB2;
        #pragma unroll
        for (int k = 0; k < 8; k++)
            #pragma unroll
            for (int o = 16; o > 0; o >>= 1)
                v[k] += __shfl_down_sync(0xffffffffu, v[k], o);
        if (lane == 0)
            #pragma unroll
            for (int k = 0; k < 8; k++) s_ws[w][k] = v[k];
        __syncthreads();

        if (tid < 8) {
            int lpi = tid >> 1, sub = tid & 1, off = sub*4;
            float sw = s_ws[lpi][off]     + s_ws[lpi+4][off];
            float ax = s_ws[lpi][off+1]   + s_ws[lpi+4][off+1];
            float ay = s_ws[lpi][off+2]   + s_ws[lpi+4][off+2];
            float az = s_ws[lpi][off+3]   + s_ws[lpi+4][off+3];
            float lx = s_ligc[tid][0], ly = s_ligc[tid][1], lz = s_ligc[tid][2];
            float nx = q0v*lx + q1v*ly + q2v*lz + t0;
            float ny = q3v*lx + q4v*ly + q5v*lz + t1;
            float nz = q6v*lx + q7v*ly + q8v*lz + t2;
            const float Cc = -2.f / 8388608.f;     // -2/(L*R)
            float gx = Cc * fmaf(0.5f, ax, sw*nx); // ax holds -2*sum(w*rx)
            float gy = Cc * fmaf(0.5f, ay, sw*ny);
            float gz = Cc * fmaf(0.5f, az, sw*nz);
            s_red12[tid][0]=gx;    s_red12[tid][1]=gy;    s_red12[tid][2]=gz;
            s_red12[tid][3]=gx*lx; s_red12[tid][4]=gx*ly; s_red12[tid][5]=gx*lz;
            s_red12[tid][6]=gy*lx; s_red12[tid][7]=gy*ly; s_red12[tid][8]=gy*lz;
            s_red12[tid][9]=gz*lx; s_red12[tid][10]=gz*ly; s_red12[tid][11]=gz*lz;
        }
        __syncthreads();
        if (tid < 12) {
            float t = 0.f;
            #pragma unroll
            for (int i = 0; i < 8; i++) t += s_red12[i][tid];
            atomicAdd(&g_accP[s][tid*32], t);      // 12 separate 128B lines
        }
        __syncthreads();
        if (tid == 0) {
            __threadfence();
            atomicAdd(&g_arr[s], 1u);
        }
    }
}

extern "C" void kernel_launch(void* const* d_in, const int* in_sizes, int n_in,
                              void* d_out, int out_size) {
    const float* lig_feat  = (const float*)d_in[0];
    const float* rec_feat  = (const float*)d_in[1];
    const float* lig_coord = (const float*)d_in[2];
    const float* rec_coord = (const float*)d_in[3];
    const float* pre_rot   = (const float*)d_in[4];
    const float* trans     = (const float*)d_in[5];
    float* out = (float*)d_out;

    static bool attr_set = false;
    if (!attr_set) {
        cudaFuncSetAttribute(k_steps, cudaFuncAttributeMaxDynamicSharedMemorySize,
                             163840);   // 128KB coords(+K) + 32KB atn ring
        attr_set = true;
    }

    k_atn<<<dim3(Rr/64, Lq/128), 256>>>(lig_feat, rec_feat);
    k_steps<<<NBS, NTS, 163840>>>(lig_coord, rec_coord, pre_rot, trans, out);
}

// round 15
// speedup vs baseline: 1.0997x; 1.0038x over previous
#include <cuda_runtime.h>
#include <math.h>
#include <stdint.h>

#define Lq 1024
#define Rr 8192
#define NBS 128
#define NTS 256

typedef unsigned long long u64;

// ---------------- scratch (device globals; no allocs allowed) ----------------
__device__ float g_atn[(size_t)Lq * Rr];     // [l][r] 32MB, L2-resident
__device__ float g_accP[7][12*32];           // per-step grad sums, 128B element stride
__device__ unsigned g_arr[7];                // per-step arrival counters
__device__ unsigned g_cnt;                   // init gridbar counter
__device__ unsigned g_sense;                 // init gridbar sense

__device__ __forceinline__ float frcp(float x) {
    float y; asm("rcp.approx.f32 %0, %1;" : "=f"(y) : "f"(x)); return y;
}
__device__ __forceinline__ u64 pk2(float lo, float hi) {
    u64 r; asm("mov.b64 %0, {%1, %2};" : "=l"(r) : "f"(lo), "f"(hi)); return r;
}
__device__ __forceinline__ void up2(u64 v, float& a, float& b) {
    asm("mov.b64 {%0, %1}, %2;" : "=f"(a), "=f"(b) : "l"(v));
}
__device__ __forceinline__ u64 add2(u64 a, u64 b) {
    u64 d; asm("add.rn.f32x2 %0, %1, %2;" : "=l"(d) : "l"(a), "l"(b)); return d;
}
__device__ __forceinline__ u64 mul2(u64 a, u64 b) {
    u64 d; asm("mul.rn.f32x2 %0, %1, %2;" : "=l"(d) : "l"(a), "l"(b)); return d;
}
__device__ __forceinline__ u64 fma2(u64 a, u64 b, u64 c) {
    u64 d; asm("fma.rn.f32x2 %0, %1, %2, %3;" : "=l"(d) : "l"(a), "l"(b), "l"(c)); return d;
}
__device__ __forceinline__ unsigned ldacq(const unsigned* p) {
    unsigned v; asm volatile("ld.acquire.gpu.u32 %0, [%1];" : "=r"(v) : "l"(p) : "memory"); return v;
}
__device__ __forceinline__ float ldacqf(const float* p) {
    float v; asm volatile("ld.acquire.gpu.f32 %0, [%1];" : "=f"(v) : "l"(p) : "memory"); return v;
}
__device__ __forceinline__ void strel(unsigned* p, unsigned v) {
    asm volatile("st.release.gpu.u32 [%0], %1;" :: "l"(p), "r"(v) : "memory");
}
__device__ __forceinline__ void cpasync16(unsigned dst, const void* src) {
    asm volatile("cp.async.cg.shared.global [%0], [%1], 16;" :: "r"(dst), "l"(src) : "memory");
}

// sense-reversing grid barrier (once at init); self-resetting across replays.
__device__ __forceinline__ void gridbar(unsigned& sense) {
    __syncthreads();
    if (threadIdx.x == 0) {
        unsigned ns = sense ^ 1u;
        __threadfence();
        unsigned old = atomicAdd(&g_cnt, 1u);
        if (old == NBS - 1u) {
            atomicExch(&g_cnt, 0u);
            strel(&g_sense, ns);
        } else {
            while (ldacq(&g_sense) != ns) {}
        }
    }
    __syncthreads();
    sense ^= 1u;
}

// LAPACK-convention Householder QR of a 3x3 (geqrf+orgqr signs).
__device__ void qr3(const float* A, float* Q, float* Rm) {
    float M[9];
    #pragma unroll
    for (int i = 0; i < 9; i++) M[i] = A[i];
    float Qa[9] = {1.f,0.f,0.f, 0.f,1.f,0.f, 0.f,0.f,1.f};
    #pragma unroll
    for (int k = 0; k < 2; k++) {
        float alpha = M[k*3+k];
        float xn2 = 0.f;
        for (int j = k+1; j < 3; j++) xn2 += M[j*3+k]*M[j*3+k];
        if (xn2 == 0.f) continue;
        float nrm  = sqrtf(alpha*alpha + xn2);
        float beta = (alpha >= 0.f) ? -nrm : nrm;
        float v[3] = {0.f,0.f,0.f};
        v[k] = 1.f;
        float denom = alpha - beta;
        for (int j = k+1; j < 3; j++) v[j] = M[j*3+k] / denom;
        float tau = (beta - alpha) / beta;
        for (int c = k; c < 3; c++) {
            float s = 0.f;
            for (int j = k; j < 3; j++) s += v[j]*M[j*3+c];
            s *= tau;
            for (int j = k; j < 3; j++) M[j*3+c] -= s*v[j];
        }
        M[k*3+k] = beta;
        for (int j = k+1; j < 3; j++) M[j*3+k] = 0.f;
        for (int i = 0; i < 3; i++) {
            float s = 0.f;
            for (int j = k; j < 3; j++) s += Qa[i*3+j]*v[j];
            s *= tau;
            for (int j = k; j < 3; j++) Qa[i*3+j] -= s*v[j];
        }
    }
    #pragma unroll
    for (int i = 0; i < 9; i++) { Q[i] = Qa[i]; Rm[i] = M[i]; }
}

__device__ __forceinline__ float blockSum(float v, float* s8) {
    #pragma unroll
    for (int o = 16; o > 0; o >>= 1) v += __shfl_down_sync(0xffffffffu, v, o);
    __syncthreads();
    if ((threadIdx.x & 31) == 0) s8[threadIdx.x >> 5] = v;
    __syncthreads();
    float t = s8[0];
    #pragma unroll
    for (int i = 1; i < 8; i++) t += s8[i];
    return t;
}

// ---------------- atn[l][r] = dot(lig_feat[l], rec_feat[r]) -------------------
// 8l x 4r register tile, 128l x 64r block tile, packed f32x2; 2 blocks/SM.
__global__ void __launch_bounds__(256, 2) k_atn(const float* __restrict__ lig_feat,
                                                const float* __restrict__ rec_feat) {
    __shared__ float4 ligs4[128*16];
    __shared__ float4 recs4[64*16];
    int tid = threadIdx.x;
    int tx = tid & 15;       // r-lane
    int ty = tid >> 4;       // l-group (8 rows)
    int r0 = blockIdx.x * 64;
    int l0 = blockIdx.y * 128;
    const float4* ligf4 = (const float4*)lig_feat;
    const float4* recf4 = (const float4*)rec_feat;
    #pragma unroll
    for (int i = 0; i < 8; i++) {
        int idx = i*256 + tid;
        int row = idx >> 4;
        int f4  = idx & 15;
        ligs4[row*16 + (f4 ^ (row & 7))] = ligf4[(size_t)(l0+row)*16 + f4];
    }
    #pragma unroll
    for (int i = 0; i < 4; i++) {
        int idx = i*256 + tid;
        int row = idx >> 4;
        int f4  = idx & 15;
        recs4[row*16 + (f4 ^ (row & 7))] = recf4[(size_t)(r0+row)*16 + f4];
    }
    __syncthreads();

    u64 acc[8][4];
    #pragma unroll
    for (int j = 0; j < 8; j++)
        #pragma unroll
        for (int i = 0; i < 4; i++) acc[j][i] = 0ull;

    #pragma unroll
    for (int f4 = 0; f4 < 16; f4++) {
        ulonglong2 a[4];
        #pragma unroll
        for (int i = 0; i < 4; i++) {
            int row = tx + 16*i;
            a[i] = *(const ulonglong2*)&recs4[row*16 + (f4 ^ (row & 7))];
        }
        #pragma unroll
        for (int j = 0; j < 8; j++) {
            int row = ty*8 + j;
            ulonglong2 bv = *(const ulonglong2*)&ligs4[row*16 + (f4 ^ (row & 7))];
            #pragma unroll
            for (int i = 0; i < 4; i++) {
                acc[j][i] = fma2(a[i].x, bv.x, acc[j][i]);
                acc[j][i] = fma2(a[i].y, bv.y, acc[j][i]);
            }
        }
    }
    #pragma unroll
    for (int j = 0; j < 8; j++) {
        size_t rowbase = (size_t)(l0 + ty*8 + j) * Rr + r0;
        #pragma unroll
        for (int i = 0; i < 4; i++) {
            float lo, hi; up2(acc[j][i], lo, hi);
            g_atn[rowbase + tx + 16*i] = lo + hi;
        }
    }
}

// expansion form: d2 = (K + |nl|^2) + cx*nx + cy*ny + cz*nz, with c = -2*rc.
// paired reciprocal: 1 MUFU per 2 r's.
#define PAIR_BODY(Av0, Av1, cx, cy, cz, kk)                                     \
    {                                                                           \
        u64 d = add2(kk, B0);                                                   \
        d = fma2(cz, Z0, d); d = fma2(cy, Y0, d); d = fma2(cx, X0, d);          \
        float dl, dh; up2(d, dl, dh);                                           \
        float rp = frcp(dl*dh);                                                 \
        u64 inv = pk2(dh*rp, dl*rp);                                            \
        u64 i4 = mul2(inv, inv);                                                \
        u64 wv = mul2(Av0, i4);                                                 \
        sw0 = add2(sw0, wv);                                                    \
        ax0 = fma2(wv, cx, ax0); ay0 = fma2(wv, cy, ay0); az0 = fma2(wv, cz, az0); \
        d = add2(kk, B1);                                                       \
        d = fma2(cz, Z1, d); d = fma2(cy, Y1, d); d = fma2(cx, X1, d);          \
        up2(d, dl, dh);                                                         \
        rp = frcp(dl*dh);                                                       \
        inv = pk2(dh*rp, dl*rp);                                                \
        i4 = mul2(inv, inv);                                                    \
        wv = mul2(Av1, i4);                                                     \
        sw1 = add2(sw1, wv);                                                    \
        ax1 = fma2(wv, cx, ax1); ay1 = fma2(wv, cy, ay1); az1 = fma2(wv, cz, az1); \
    }

// prefetch chunk c (128 r's) into ring stage (c&3): 2 x 16B per lane
#define PREFETCH(c)                                                             \
    {                                                                           \
        unsigned d0 = sb_w + (((c) & 3)*256 + lane*4)*4;                        \
        cpasync16(d0,       ga0 + (c)*128 + lane*4);                            \
        cpasync16(d0 + 512, ga1 + (c)*128 + lane*4);                            \
        asm volatile("cp.async.commit_group;" ::: "memory");                    \
    }

// compute chunk c from ring stage (c&3): 4 r per lane x 2 l
#define CHUNK(c)                                                                \
    {                                                                           \
        const float4 a0 = *(const float4*)(s_atn_w + ((c) & 3)*256 + lane*4);   \
        const float4 a1 = *(const float4*)(s_atn_w + ((c) & 3)*256 + 128 + lane*4); \
        int idx = (c)*32 + lane;                                                \
        ulonglong2 vx = pX[idx], vy = pY[idx], vz = pZ[idx], vk = pK[idx];      \
        PAIR_BODY(pk2(a0.x,a0.y), pk2(a1.x,a1.y), vx.x, vy.x, vz.x, vk.x);      \
        PAIR_BODY(pk2(a0.z,a0.w), pk2(a1.z,a1.w), vx.y, vy.y, vz.y, vk.y);      \
    }

// ---------------- persistent kernel: preps + all 8 steps ----------------------
__global__ void __launch_bounds__(NTS, 1) k_steps(const float* __restrict__ lig_coord,
                                                  const float* __restrict__ rec_coord,
                                                  const float* __restrict__ pre_rot,
                                                  const float* __restrict__ trans,
                                                  float* __restrict__ out) {
    extern __shared__ float sm[];
    u64* cX = (u64*)sm;                  // [4096] packed r-pairs of -2*(x - mx)
    u64* cY = cX + 4096;
    u64* cZ = cY + 4096;
    u64* cK = cZ + 4096;                 // [4096] packed |rc|^2
    float* s_atn = sm + 32768;           // [8 warps][4 stages][2 l][128 r] = 32KB
    __shared__ float s_red[8];
    __shared__ float s_ws[8][8];
    __shared__ float s_red12[8][12];
    __shared__ float s_ligc[8][3];
    __shared__ float s_upd[12];          // current-step Q(9)+tr(3)
    __shared__ float s_t[12];            // fetched global gradient sums

    int tid = threadIdx.x, b = blockIdx.x;
    int w = tid >> 5, lane = tid & 31;
    int lp = w & 3, h = w >> 2;                // l-pair idx (0..3), r-half (0..1)
    int l0 = b*8 + lp*2;                       // warp handles l0, l0+1

    unsigned sense;
    { volatile unsigned* gs = &g_sense; sense = *gs; }

    const float* ga0 = g_atn + (size_t)l0*Rr     + h*4096;
    const float* ga1 = g_atn + (size_t)(l0+1)*Rr + h*4096;
    const float* s_atn_w = s_atn + w*1024;
    unsigned sb_w = (unsigned)__cvta_generic_to_shared(s_atn_w);

    // ---- initial ring fill for step 0: overlaps ALL of prep below ----
    PREFETCH(0); PREFETCH(1); PREFETCH(2); PREFETCH(3);

    // ---- rec means ----
    float sx = 0.f, sy = 0.f, sz = 0.f;
    for (int i = tid; i < Rr; i += NTS) {
        sx += rec_coord[3*i]; sy += rec_coord[3*i+1]; sz += rec_coord[3*i+2];
    }
    float mx = blockSum(sx, s_red) * (1.f/Rr);
    float my = blockSum(sy, s_red) * (1.f/Rr);
    float mz = blockSum(sz, s_red) * (1.f/Rr);

    // ---- build -2*centered coords + |rc|^2 (4 r's per thread-iter) ----
    {
        const float4* rc4 = (const float4*)rec_coord;
        ulonglong2* vX = (ulonglong2*)cX;
        ulonglong2* vY = (ulonglong2*)cY;
        ulonglong2* vZ = (ulonglong2*)cZ;
        ulonglong2* vK = (ulonglong2*)cK;
        for (int p4 = tid; p4 < Rr/4; p4 += NTS) {
            float4 f0 = rc4[3*p4], f1 = rc4[3*p4+1], f2 = rc4[3*p4+2];
            float x0 = f0.x - mx, y0 = f0.y - my, z0 = f0.z - mz;
            float x1 = f0.w - mx, y1 = f1.x - my, z1 = f1.y - mz;
            float x2 = f1.z - mx, y2 = f1.w - my, z2 = f2.x - mz;
            float x3 = f2.y - mx, y3 = f2.z - my, z3 = f2.w - mz;
            float k0 = x0*x0 + y0*y0 + z0*z0;
            float k1 = x1*x1 + y1*y1 + z1*z1;
            float k2 = x2*x2 + y2*y2 + z2*z2;
            float k3 = x3*x3 + y3*y3 + z3*z3;
            ulonglong2 ox, oy, oz, ok;
            ox.x = pk2(-2.f*x0, -2.f*x1); ox.y = pk2(-2.f*x2, -2.f*x3);
            oy.x = pk2(-2.f*y0, -2.f*y1); oy.y = pk2(-2.f*y2, -2.f*y3);
            oz.x = pk2(-2.f*z0, -2.f*z1); oz.y = pk2(-2.f*z2, -2.f*z3);
            ok.x = pk2(k0, k1);           ok.y = pk2(k2, k3);
            vX[p4] = ox; vY[p4] = oy; vZ[p4] = oz; vK[p4] = ok;
        }
    }

    // ---- lig means + centered coords for this block's 8 l's ----
    float lsx = 0.f, lsy = 0.f, lsz = 0.f;
    for (int i = tid; i < Lq; i += NTS) {
        lsx += lig_coord[3*i]; lsy += lig_coord[3*i+1]; lsz += lig_coord[3*i+2];
    }
    float mlx = blockSum(lsx, s_red) * (1.f/Lq);
    float mly = blockSum(lsy, s_red) * (1.f/Lq);
    float mlz = blockSum(lsz, s_red) * (1.f/Lq);
    if (tid < 8) {
        int l = b*8 + tid;
        s_ligc[tid][0] = lig_coord[3*l]   - mlx;
        s_ligc[tid][1] = lig_coord[3*l+1] - mly;
        s_ligc[tid][2] = lig_coord[3*l+2] - mlz;
    }

    // ---- per-block optimizer state (identical in every block: deterministic) ----
    float pr[9], trv[3], Q[9], Rm[9];
    if (tid == 0) {
        #pragma unroll
        for (int i = 0; i < 9; i++) pr[i] = pre_rot[i];
        #pragma unroll
        for (int i = 0; i < 3; i++) trv[i] = trans[i] * 4.0f;   // TRANS_DIST
        qr3(pr, Q, Rm);
        #pragma unroll
        for (int i = 0; i < 9; i++) s_upd[i] = Q[i];
        #pragma unroll
        for (int i = 0; i < 3; i++) s_upd[9+i] = trv[i];
    }

    // ---- block 0 zeroes the per-step accumulators/counters ----
    if (b == 0) {
        for (int i = tid; i < 7*12*32; i += NTS) ((float*)g_accP)[i] = 0.f;
        if (tid < 7) g_arr[tid] = 0u;
    }
    gridbar(sense);   // accumulators zeroed + smem coords/params ready

    float lx0 = s_ligc[lp*2][0],   ly0 = s_ligc[lp*2][1],   lz0 = s_ligc[lp*2][2];
    float lx1 = s_ligc[lp*2+1][0], ly1 = s_ligc[lp*2+1][1], lz1 = s_ligc[lp*2+1][2];

    const ulonglong2* pX = (const ulonglong2*)cX + h*1024;
    const ulonglong2* pY = (const ulonglong2*)cY + h*1024;
    const ulonglong2* pZ = (const ulonglong2*)cZ + h*1024;
    const ulonglong2* pK = (const ulonglong2*)cK + h*1024;

    for (int s = 0; s < 8; s++) {
        // ---- for s>0: wait for step s-1 reduction, update locally ----
        // (ring for this step was prefetched at the end of step s-1's loop)
        if (s > 0) {
            if (tid == 0) {
                while (ldacq(&g_arr[s-1]) < NBS) __nanosleep(64);
            }
            __syncthreads();
            if (tid < 12) s_t[tid] = ldacqf(&g_accP[s-1][tid*32]);
            __syncthreads();
            if (tid == 0) {
                float t[12];
                #pragma unroll
                for (int k = 0; k < 12; k++) t[k] = s_t[k];
                float G0=t[3],G1=t[4],G2=t[5],G3=t[6],G4=t[7],G5=t[8],G6=t[9],G7=t[10],G8=t[11];
                float S10 = Q[1]*G0 + Q[4]*G3 + Q[7]*G6;
                float S01 = Q[0]*G1 + Q[3]*G4 + Q[6]*G7;
                float S20 = Q[2]*G0 + Q[5]*G3 + Q[8]*G6;
                float S02 = Q[0]*G2 + Q[3]*G5 + Q[6]*G8;
                float S21 = Q[2]*G1 + Q[5]*G4 + Q[8]*G7;
                float S12 = Q[1]*G2 + Q[4]*G5 + Q[7]*G8;
                float b10 = S10 - S01, b20 = S20 - S02, b21 = S21 - S12;
                float T10 = b10 / Rm[0];
                float T21 = b21 / Rm[4];
                float T20 = (b20 - T21*Rm[1]) / Rm[0];
                #pragma unroll
                for (int i = 0; i < 3; i++) {
                    pr[i*3+0] -= Q[i*3+1]*T10 + Q[i*3+2]*T20;   // ROT_LR=1
                    pr[i*3+1] -= Q[i*3+2]*T21;
                }
                #pragma unroll
                for (int i = 0; i < 3; i++) trv[i] -= 0.1f * t[i];   // TRANS_LR
                qr3(pr, Q, Rm);
                #pragma unroll
                for (int i = 0; i < 9; i++) s_upd[i] = Q[i];
                #pragma unroll
                for (int i = 0; i < 3; i++) s_upd[9+i] = trv[i];
            }
            __syncthreads();
        }

        // ---- forward ----
        float q0v=s_upd[0],q1v=s_upd[1],q2v=s_upd[2],q3v=s_upd[3],q4v=s_upd[4],
              q5v=s_upd[5],q6v=s_upd[6],q7v=s_upd[7],q8v=s_upd[8];
        float t0=s_upd[9],t1=s_upd[10],t2=s_upd[11];
        float nx0 = q0v*lx0 + q1v*ly0 + q2v*lz0 + t0;
        float ny0 = q3v*lx0 + q4v*ly0 + q5v*lz0 + t1;
        float nz0 = q6v*lx0 + q7v*ly0 + q8v*lz0 + t2;
        float nx1 = q0v*lx1 + q1v*ly1 + q2v*lz1 + t0;
        float ny1 = q3v*lx1 + q4v*ly1 + q5v*lz1 + t1;
        float nz1 = q6v*lx1 + q7v*ly1 + q8v*lz1 + t2;
        if (h == 0 && lane == 0) {
            float* o = out + (size_t)s*3*Lq + 3*l0;
            o[0]=nx0; o[1]=ny0; o[2]=nz0; o[3]=nx1; o[4]=ny1; o[5]=nz1;
        }
        if (s == 7) break;

        u64 X0 = pk2(nx0,nx0), Y0 = pk2(ny0,ny0), Z0 = pk2(nz0,nz0);
        u64 X1 = pk2(nx1,nx1), Y1 = pk2(ny1,ny1), Z1 = pk2(nz1,nz1);
        float b0f = nx0*nx0 + ny0*ny0 + nz0*nz0;
        float b1f = nx1*nx1 + ny1*ny1 + nz1*nz1;
        u64 B0 = pk2(b0f,b0f), B1 = pk2(b1f,b1f);
        u64 sw0 = 0ull, ax0 = 0ull, ay0 = 0ull, az0 = 0ull;
        u64 sw1 = 0ull, ax1 = 0ull, ay1 = 0ull, az1 = 0ull;

        // ---- streamed pair loop: 32 chunks, 4-deep cp.async pipeline ----
        #pragma unroll 4
        for (int c = 0; c < 28; c++) {
            asm volatile("cp.async.wait_group 3;" ::: "memory");
            CHUNK(c);
            PREFETCH(c + 4);
        }
        asm volatile("cp.async.wait_group 3;" ::: "memory"); CHUNK(28);
        asm volatile("cp.async.wait_group 2;" ::: "memory"); CHUNK(29);
        asm volatile("cp.async.wait_group 1;" ::: "memory"); CHUNK(30);
        asm volatile("cp.async.wait_group 0;" ::: "memory"); CHUNK(31);

        // ---- prefetch next step's first 4 chunks NOW: overlaps the whole
        //      reduction tail + arrival + poll (atn is step-invariant) ----
        if (s < 6) { PREFETCH(0); PREFETCH(1); PREFETCH(2); PREFETCH(3); }

        // ---- warp reduce -> smem -> block partials -> spread global atomics ----
        float v[8], tA, tB2;
        up2(sw0, tA, tB2); v[0] = tA + tB2;
        up2(ax0, tA, tB2); v[1] = tA + tB2;
        up2(ay0, tA, tB2); v[2] = tA + tB2;
        up2(az0, tA, tB2); v[3] = tA + tB2;
        up2(sw1, tA, tB2); v[4] = tA + tB2;
        up2(ax1, tA, tB2); v[5] = tA + tB2;
        up2(ay1, tA, tB2); v[6] = tA + tB2;
        up2(az1, tA, tB2); v[7] = tA + tB2;
        #pragma unroll
        for (int k = 0; k < 8; k++)
            #pragma unroll
            for (int o = 16; o > 0; o >>= 1)
                v[k] += __shfl_down_sync(0xffffffffu, v[k], o);
        if (lane == 0)
            #pragma unroll
            for (int k = 0; k < 8; k++) s_ws[w][k] = v[k];
        __syncthreads();

        if (tid < 8) {
            int lpi = tid >> 1, sub = tid & 1, off = sub*4;
            float sw = s_ws[lpi][off]     + s_ws[lpi+4][off];
            float ax = s_ws[lpi][off+1]   + s_ws[lpi+4][off+1];
            float ay = s_ws[lpi][off+2]   + s_ws[lpi+4][off+2];
            float az = s_ws[lpi][off+3]   + s_ws[lpi+4][off+3];
            float lx = s_ligc[tid][0], ly = s_ligc[tid][1], lz = s_ligc[tid][2];
            float nx = q0v*lx + q1v*ly + q2v*lz + t0;
            float ny = q3v*lx + q4v*ly + q5v*lz + t1;
            float nz = q6v*lx + q7v*ly + q8v*lz + t2;
            const float Cc = -2.f / 8388608.f;     // -2/(L*R)
            float gx = Cc * fmaf(0.5f, ax, sw*nx); // ax holds -2*sum(w*rx)
            float gy = Cc * fmaf(0.5f, ay, sw*ny);
            float gz = Cc * fmaf(0.5f, az, sw*nz);
            s_red12[tid][0]=gx;    s_red12[tid][1]=gy;    s_red12[tid][2]=gz;
            s_red12[tid][3]=gx*lx; s_red12[tid][4]=gx*ly; s_red12[tid][5]=gx*lz;
            s_red12[tid][6]=gy*lx; s_red12[tid][7]=gy*ly; s_red12[tid][8]=gy*lz;
            s_red12[tid][9]=gz*lx; s_red12[tid][10]=gz*ly; s_red12[tid][11]=gz*lz;
        }
        __syncthreads();
        if (tid < 12) {
            float t = 0.f;
            #pragma unroll
            for (int i = 0; i < 8; i++) t += s_red12[i][tid];
            atomicAdd(&g_accP[s][tid*32], t);      // 12 separate 128B lines
        }
        __syncthreads();
        if (tid == 0) {
            __threadfence();
            atomicAdd(&g_arr[s], 1u);
        }
    }
}

extern "C" void kernel_launch(void* const* d_in, const int* in_sizes, int n_in,
                              void* d_out, int out_size) {
    const float* lig_feat  = (const float*)d_in[0];
    const float* rec_feat  = (const float*)d_in[1];
    const float* lig_coord = (const float*)d_in[2];
    const float* rec_coord = (const float*)d_in[3];
    const float* pre_rot   = (const float*)d_in[4];
    const float* trans     = (const float*)d_in[5];
    float* out = (float*)d_out;

    static bool attr_set = false;
    if (!attr_set) {
        cudaFuncSetAttribute(k_steps, cudaFuncAttributeMaxDynamicSharedMemorySize,
                             163840);   // 128KB coords(+K) + 32KB atn ring
        attr_set = true;
    }

    k_atn<<<dim3(Rr/64, Lq/128), 256>>>(lig_feat, rec_feat);
    k_steps<<<NBS, NTS, 163840>>>(lig_coord, rec_coord, pre_rot, trans, out);
}